// round 10
// baseline (speedup 1.0000x reference)
#include <cuda_runtime.h>
#include <cuda_fp16.h>
#include <math.h>
#include <stdint.h>

#define Bb 8
#define Ss 2048
#define Tt 512
#define Hh 1024
#define NH 16
#define DK 64

// ---- scratch ----
__device__ __half g_H [(size_t)Bb*Ss*Hh];
__device__ __half g_QH[(size_t)Bb*Tt*Hh];
__device__ __half g_Wq[Hh*Hh], g_Wk[Hh*Hh], g_Wv[Hh*Hh], g_Wo[Hh*Hh];
__device__ __half g_Q [(size_t)Bb*Tt*Hh];
__device__ __half g_K [(size_t)Bb*Ss*Hh];
__device__ __half g_V [(size_t)Bb*Ss*Hh];
__device__ __half g_P [(size_t)Bb*NH*Tt*Ss];
__device__ __half g_C [(size_t)Bb*Tt*Hh];

// ------------------------------------------------------------
__device__ __forceinline__ uint32_t h2u(__half2 v) { return *(uint32_t*)&v; }

__device__ __forceinline__ void mma_f16(float* c, const uint32_t* a, const uint32_t* b) {
    asm volatile(
        "mma.sync.aligned.m16n8k16.row.col.f32.f16.f16.f32 "
        "{%0,%1,%2,%3}, {%4,%5,%6,%7}, {%8,%9}, {%0,%1,%2,%3};"
        : "+f"(c[0]), "+f"(c[1]), "+f"(c[2]), "+f"(c[3])
        : "r"(a[0]), "r"(a[1]), "r"(a[2]), "r"(a[3]),
          "r"(b[0]), "r"(b[1]));
}

__device__ __forceinline__ void cpa16(void* dst, const void* src) {
    uint32_t d = (uint32_t)__cvta_generic_to_shared(dst);
    asm volatile("cp.async.cg.shared.global [%0], [%1], 16;" :: "r"(d), "l"(src));
}
__device__ __forceinline__ void cp_commit() { asm volatile("cp.async.commit_group;"); }
template<int N_> __device__ __forceinline__ void cp_wait() {
    asm volatile("cp.async.wait_group %0;" :: "n"(N_));
}

__device__ __forceinline__ void ldsm_x4(uint32_t* r, uint32_t addr) {
    asm volatile("ldmatrix.sync.aligned.m8n8.x4.shared.b16 {%0,%1,%2,%3}, [%4];"
        : "=r"(r[0]), "=r"(r[1]), "=r"(r[2]), "=r"(r[3]) : "r"(addr));
}
__device__ __forceinline__ void ldsm_x4_t(uint32_t* r, uint32_t addr) {
    asm volatile("ldmatrix.sync.aligned.m8n8.x4.trans.shared.b16 {%0,%1,%2,%3}, [%4];"
        : "=r"(r[0]), "=r"(r[1]), "=r"(r[2]), "=r"(r[3]) : "r"(addr));
}

__device__ __forceinline__ void ldA_x4(uint32_t* r, const __half* S, int LD,
                                       int row0, int col0, int lane) {
    int g = lane >> 3, rr = lane & 7;
    const __half* p = S + (size_t)(row0 + (g & 1) * 8 + rr) * LD + col0 + (g >> 1) * 8;
    ldsm_x4(r, (uint32_t)__cvta_generic_to_shared(p));
}
__device__ __forceinline__ void ldBn_x4(uint32_t* b0, uint32_t* b1,
                                        const __half* S, int LD, int n0, int k0, int lane) {
    int g = lane >> 3, rr = lane & 7;
    const __half* p = S + (n0 + (g & 1) * 8 + rr) * LD + k0 + (g >> 1) * 8;
    uint32_t q[4];
    ldsm_x4(q, (uint32_t)__cvta_generic_to_shared(p));
    b0[0] = q[0]; b0[1] = q[2];
    b1[0] = q[1]; b1[1] = q[3];
}
__device__ __forceinline__ void ldB_pair(uint32_t* b0, uint32_t* b1,
                                         const __half* S, int RS, int k0, int n0, int lane) {
    int g = lane >> 3, r = lane & 7;
    int row = k0 + r + (g & 1) * 8;
    int col = n0 + (g >> 1) * 8;
    uint32_t q[4];
    ldsm_x4_t(q, (uint32_t)__cvta_generic_to_shared(S + row * RS + col));
    b0[0] = q[0]; b0[1] = q[1];
    b1[0] = q[2]; b1[1] = q[3];
}

// ============================================================
__global__ void f2h4(const float* __restrict__ in, __half* __restrict__ out, int n4) {
    int i = blockIdx.x * blockDim.x + threadIdx.x;
    if (i < n4) {
        float4 v = ((const float4*)in)[i];
        uint2 u;
        u.x = h2u(__floats2half2_rn(v.x, v.y));
        u.y = h2u(__floats2half2_rn(v.z, v.w));
        ((uint2*)out)[i] = u;
    }
}

// ============================================================
// fp16 GEMM: 128x128 tile, BK=64, cp.async dbl-buf, 8 warps 64x32.
// ============================================================
template<bool F16OUT, bool HAS_BIAS>
__global__ void __launch_bounds__(256) gemm16(
    const __half* __restrict__ A, const __half* __restrict__ W,
    const float* __restrict__ bias, void* __restrict__ Cout,
    int M, int N, int K, float scale)
{
    extern __shared__ __half smx[];
    __half* As = smx;                  // 2 x [128][72]
    __half* Bs = smx + 2 * 128 * 72;   // 2 x [64][136]
    int tid = threadIdx.x, lane = tid & 31, wid = tid >> 5;
    int lr = lane >> 2, lc = lane & 3;
    int wm = (wid >> 2) * 64, wn = (wid & 3) * 32;
    int bx = blockIdx.x, by = blockIdx.y;

    const __half* Ag = A + (size_t)by * 128 * K;
    const __half* Wg = W + bx * 128;

    float acc[4][4][4];
    #pragma unroll
    for (int i = 0; i < 4; i++)
        #pragma unroll
        for (int j = 0; j < 4; j++)
            #pragma unroll
            for (int q = 0; q < 4; q++) acc[i][j][q] = 0.f;

    auto loadAB = [&](int buf, int k0) {
        __half* Ab = As + buf * 128 * 72;
        __half* Bb2 = Bs + buf * 64 * 136;
        #pragma unroll
        for (int j = 0; j < 4; j++) {
            int id = tid + j * 256;
            int r = id >> 3, c = (id & 7) * 8;
            cpa16(Ab + r * 72 + c, Ag + (size_t)r * K + k0 + c);
        }
        #pragma unroll
        for (int j = 0; j < 4; j++) {
            int id = tid + j * 256;
            int r = id >> 4, c = (id & 15) * 8;
            cpa16(Bb2 + r * 136 + c, Wg + (size_t)(k0 + r) * N + c);
        }
        cp_commit();
    };

    int nit = K / 64;
    loadAB(0, 0);
    for (int it = 0; it < nit; it++) {
        if (it + 1 < nit) loadAB((it + 1) & 1, (it + 1) * 64);
        if (it + 1 < nit) cp_wait<1>(); else cp_wait<0>();
        __syncthreads();
        const __half* Ab = As + (it & 1) * 128 * 72;
        const __half* Bb2 = Bs + (it & 1) * 64 * 136;
        #pragma unroll
        for (int ks = 0; ks < 64; ks += 16) {
            uint32_t a[4][4], b[4][2];
            #pragma unroll
            for (int im = 0; im < 4; im++)
                ldA_x4(a[im], Ab, 72, wm + im * 16, ks, lane);
            ldB_pair(b[0], b[1], Bb2, 136, ks, wn,      lane);
            ldB_pair(b[2], b[3], Bb2, 136, ks, wn + 16, lane);
            #pragma unroll
            for (int im = 0; im < 4; im++)
                #pragma unroll
                for (int in_ = 0; in_ < 4; in_++)
                    mma_f16(acc[im][in_], a[im], b[in_]);
        }
        __syncthreads();
    }

    #pragma unroll
    for (int im = 0; im < 4; im++) {
        #pragma unroll
        for (int in_ = 0; in_ < 4; in_++) {
            int r0 = by * 128 + wm + im * 16 + lr;
            int cb = bx * 128 + wn + in_ * 8 + 2 * lc;
            float b0 = HAS_BIAS ? bias[cb] : 0.f;
            float b1 = HAS_BIAS ? bias[cb + 1] : 0.f;
            float x0 = (acc[im][in_][0] + b0) * scale;
            float x1 = (acc[im][in_][1] + b1) * scale;
            float x2 = (acc[im][in_][2] + b0) * scale;
            float x3 = (acc[im][in_][3] + b1) * scale;
            if (F16OUT) {
                __half* C = (__half*)Cout;
                *(__half2*)(C + (size_t)r0 * N + cb)       = __floats2half2_rn(x0, x1);
                *(__half2*)(C + (size_t)(r0 + 8) * N + cb) = __floats2half2_rn(x2, x3);
            } else {
                float* C = (float*)Cout;
                *(float2*)(C + (size_t)r0 * N + cb)       = make_float2(x0, x1);
                *(float2*)(C + (size_t)(r0 + 8) * N + cb) = make_float2(x2, x3);
            }
        }
    }
}

// ============================================================
// Fused K+V projection (legacy HMMA)
// ============================================================
__global__ void __launch_bounds__(256, 1) kvgemm16(
    const __half* __restrict__ A, const __half* __restrict__ Wk,
    const __half* __restrict__ Wv, __half* __restrict__ Ko,
    __half* __restrict__ Vo)
{
    const int N = Hh, K = Hh;
    extern __shared__ __half smk[];
    __half* As  = smk;                    // 2 x [128][72]
    __half* Bks = smk + 2 * 128 * 72;     // 2 x [64][136]
    __half* Bvs = Bks + 2 * 64 * 136;     // 2 x [64][136]
    int tid = threadIdx.x, lane = tid & 31, wid = tid >> 5;
    int lr = lane >> 2, lc = lane & 3;
    int wm = (wid >> 2) * 64, wn = (wid & 3) * 32;
    int bx = blockIdx.x, by = blockIdx.y;

    const __half* Ag  = A  + (size_t)by * 128 * K;
    const __half* Wkg = Wk + bx * 128;
    const __half* Wvg = Wv + bx * 128;

    float accK[4][4][4], accV[4][4][4];
    #pragma unroll
    for (int i = 0; i < 4; i++)
        #pragma unroll
        for (int j = 0; j < 4; j++)
            #pragma unroll
            for (int q = 0; q < 4; q++) { accK[i][j][q] = 0.f; accV[i][j][q] = 0.f; }

    auto loadAB = [&](int buf, int k0) {
        __half* Ab  = As  + buf * 128 * 72;
        __half* Bkb = Bks + buf * 64 * 136;
        __half* Bvb = Bvs + buf * 64 * 136;
        #pragma unroll
        for (int j = 0; j < 4; j++) {
            int id = tid + j * 256;
            int r = id >> 3, c = (id & 7) * 8;
            cpa16(Ab + r * 72 + c, Ag + (size_t)r * K + k0 + c);
        }
        #pragma unroll
        for (int j = 0; j < 4; j++) {
            int id = tid + j * 256;
            int r = id >> 4, c = (id & 15) * 8;
            cpa16(Bkb + r * 136 + c, Wkg + (size_t)(k0 + r) * N + c);
            cpa16(Bvb + r * 136 + c, Wvg + (size_t)(k0 + r) * N + c);
        }
        cp_commit();
    };

    const int nit = K / 64;
    loadAB(0, 0);
    for (int it = 0; it < nit; it++) {
        if (it + 1 < nit) loadAB((it + 1) & 1, (it + 1) * 64);
        if (it + 1 < nit) cp_wait<1>(); else cp_wait<0>();
        __syncthreads();
        const __half* Ab  = As  + (it & 1) * 128 * 72;
        const __half* Bkb = Bks + (it & 1) * 64 * 136;
        const __half* Bvb = Bvs + (it & 1) * 64 * 136;
        #pragma unroll
        for (int ks = 0; ks < 64; ks += 16) {
            uint32_t a[4][4], bk[4][2], bv[4][2];
            #pragma unroll
            for (int im = 0; im < 4; im++)
                ldA_x4(a[im], Ab, 72, wm + im * 16, ks, lane);
            ldB_pair(bk[0], bk[1], Bkb, 136, ks, wn,      lane);
            ldB_pair(bk[2], bk[3], Bkb, 136, ks, wn + 16, lane);
            ldB_pair(bv[0], bv[1], Bvb, 136, ks, wn,      lane);
            ldB_pair(bv[2], bv[3], Bvb, 136, ks, wn + 16, lane);
            #pragma unroll
            for (int im = 0; im < 4; im++)
                #pragma unroll
                for (int in_ = 0; in_ < 4; in_++) {
                    mma_f16(accK[im][in_], a[im], bk[in_]);
                    mma_f16(accV[im][in_], a[im], bv[in_]);
                }
        }
        __syncthreads();
    }

    #pragma unroll
    for (int im = 0; im < 4; im++) {
        #pragma unroll
        for (int in_ = 0; in_ < 4; in_++) {
            int r0 = by * 128 + wm + im * 16 + lr;
            int cb = bx * 128 + wn + in_ * 8 + 2 * lc;
            *(__half2*)(Ko + (size_t)r0 * N + cb) =
                __floats2half2_rn(accK[im][in_][0], accK[im][in_][1]);
            *(__half2*)(Ko + (size_t)(r0 + 8) * N + cb) =
                __floats2half2_rn(accK[im][in_][2], accK[im][in_][3]);
            *(__half2*)(Vo + (size_t)r0 * N + cb) =
                __floats2half2_rn(accV[im][in_][0], accV[im][in_][1]);
            *(__half2*)(Vo + (size_t)(r0 + 8) * N + cb) =
                __floats2half2_rn(accV[im][in_][2], accV[im][in_][3]);
        }
    }
}

// ============================================================
// Fused scores + softmax + AV. 512 threads, 32 t-rows.
// Phase 1: S = QK^T into Es. Phase 2: softmax -> global P + Es.
// Phase 3: C = P V from Es (V streamed through K buffers).
// ============================================================
__global__ void __launch_bounds__(512) scores_softmax_av(
    const __half* __restrict__ Q, const __half* __restrict__ Kg,
    const __half* __restrict__ Vg, const int* __restrict__ mask,
    __half* __restrict__ P, __half* __restrict__ Cc)
{
    extern __shared__ __half sms[];
    __half* Es = sms;                 // [32][2056]
    __half* Ks = sms + 32 * 2056;     // 2 x [256][72]  (reused for V)
    __half* Qs = Ks + 2 * 256 * 72;   // [32][72]

    int tid = threadIdx.x, lane = tid & 31, wid = tid >> 5;
    int lr = lane >> 2, lc = lane & 3;
    int bh = blockIdx.y, b = bh >> 4, h = bh & 15;
    int t0 = blockIdx.x * 32;
    int n0 = wid * 16;

    if (tid < 256) {
        int r = tid >> 3, c = (tid & 7) * 8;
        *(uint4*)&Qs[r * 72 + c] =
            *(const uint4*)(Q + (size_t)(b * Tt + t0 + r) * Hh + h * DK + c);
    }

    auto loadKV = [&](const __half* src, int buf, int s0) {
        __half* Kb = Ks + buf * 256 * 72;
        #pragma unroll
        for (int j = 0; j < 4; j++) {
            int id = tid + j * 512;
            int r = id >> 3, c = (id & 7) * 8;
            cpa16(Kb + r * 72 + c, src + (size_t)(b * Ss + s0 + r) * Hh + h * DK + c);
        }
        cp_commit();
    };

    loadKV(Kg, 0, 0);
    __syncthreads();

    uint32_t qa[2][4][4];
    #pragma unroll
    for (int im = 0; im < 2; im++)
        #pragma unroll
        for (int kk = 0; kk < 4; kk++)
            ldA_x4(qa[im][kk], Qs, 72, im * 16, kk * 16, lane);

    // ---- Phase 1: scores ----
    for (int it = 0; it < 8; it++) {
        if (it + 1 < 8) loadKV(Kg, (it + 1) & 1, (it + 1) * 256);
        if (it + 1 < 8) cp_wait<1>(); else cp_wait<0>();
        __syncthreads();
        const __half* Kb = Ks + (it & 1) * 256 * 72;
        int s0 = it * 256;

        float acc[2][2][4];
        #pragma unroll
        for (int i = 0; i < 2; i++)
            #pragma unroll
            for (int j = 0; j < 2; j++)
                #pragma unroll
                for (int q = 0; q < 4; q++) acc[i][j][q] = 0.f;

        #pragma unroll
        for (int kk = 0; kk < 4; kk++) {
            uint32_t bf[2][2];
            ldBn_x4(bf[0], bf[1], Kb, 72, n0, kk * 16, lane);
            #pragma unroll
            for (int im = 0; im < 2; im++)
                #pragma unroll
                for (int in_ = 0; in_ < 2; in_++)
                    mma_f16(acc[im][in_], qa[im][kk], bf[in_]);
        }

        #pragma unroll
        for (int im = 0; im < 2; im++) {
            #pragma unroll
            for (int in_ = 0; in_ < 2; in_++) {
                int t = im * 16 + lr;
                int s = s0 + n0 + in_ * 8 + 2 * lc;
                *(__half2*)&Es[t * 2056 + s] =
                    __floats2half2_rn(acc[im][in_][0], acc[im][in_][1]);
                *(__half2*)&Es[(t + 8) * 2056 + s] =
                    __floats2half2_rn(acc[im][in_][2], acc[im][in_][3]);
            }
        }
        __syncthreads();
    }

    // Prefetch first V chunk (overlaps with softmax phase)
    loadKV(Vg, 0, 0);

    // ---- Phase 2: softmax (16 warps x 2 rows); writes P + Es ----
    const int* mrow = mask + b * Ss;
    const __half minus3e4 = __float2half(-30000.f);
    #pragma unroll
    for (int rr = 0; rr < 2; rr++) {
        int r = wid * 2 + rr;
        uint4 E[8];
        float mx = -3.0e38f;
        #pragma unroll
        for (int i = 0; i < 8; i++) {
            int s = i * 256 + lane * 8;
            E[i] = *(uint4*)&Es[r * 2056 + s];
            int4 m0 = *(const int4*)&mrow[s];
            int4 m1 = *(const int4*)&mrow[s + 4];
            __half* hp = (__half*)&E[i];
            if (!m0.x) hp[0] = minus3e4;
            if (!m0.y) hp[1] = minus3e4;
            if (!m0.z) hp[2] = minus3e4;
            if (!m0.w) hp[3] = minus3e4;
            if (!m1.x) hp[4] = minus3e4;
            if (!m1.y) hp[5] = minus3e4;
            if (!m1.z) hp[6] = minus3e4;
            if (!m1.w) hp[7] = minus3e4;
            __half2* h2p = (__half2*)&E[i];
            #pragma unroll
            for (int j = 0; j < 4; j++) {
                float2 f = __half22float2(h2p[j]);
                mx = fmaxf(mx, fmaxf(f.x, f.y));
            }
        }
        #pragma unroll
        for (int o = 16; o; o >>= 1) mx = fmaxf(mx, __shfl_xor_sync(0xffffffffu, mx, o));

        float sum = 0.f;
        #pragma unroll
        for (int i = 0; i < 8; i++) {
            __half2* h2p = (__half2*)&E[i];
            #pragma unroll
            for (int j = 0; j < 4; j++) {
                float2 f = __half22float2(h2p[j]);
                float e0 = __expf(f.x - mx), e1 = __expf(f.y - mx);
                sum += e0 + e1;
                h2p[j] = __floats2half2_rn(e0, e1);
            }
        }
        #pragma unroll
        for (int o = 16; o; o >>= 1) sum += __shfl_xor_sync(0xffffffffu, sum, o);
        float inv = 1.0f / sum;

        __half* Pd = P + ((size_t)bh * Tt + t0 + r) * Ss;
        #pragma unroll
        for (int i = 0; i < 8; i++) {
            __half2* h2p = (__half2*)&E[i];
            #pragma unroll
            for (int j = 0; j < 4; j++) {
                float2 f = __half22float2(h2p[j]);
                h2p[j] = __floats2half2_rn(f.x * inv, f.y * inv);
            }
            int s = i * 256 + lane * 8;
            *(uint4*)(Pd + s) = E[i];
            *(uint4*)&Es[r * 2056 + s] = E[i];   // normalized P back to smem
        }
    }
    __syncthreads();   // Es now holds normalized P for all 32 rows

    // ---- Phase 3: AV. warp w: m16 tile at (w&1)*16, n8 at (w>>1)*8 ----
    {
        int mrow2 = (wid & 1) * 16;
        int ncol  = (wid >> 1) * 8;
        int nbase = (ncol >> 4) * 16;
        int nsel  = (ncol >> 3) & 1;
        float acc[4] = {0.f, 0.f, 0.f, 0.f};

        for (int it = 0; it < 8; it++) {
            if (it + 1 < 8) loadKV(Vg, (it + 1) & 1, (it + 1) * 256);
            if (it + 1 < 8) cp_wait<1>(); else cp_wait<0>();
            __syncthreads();
            const __half* Vb = Ks + (it & 1) * 256 * 72;
            #pragma unroll
            for (int ks = 0; ks < 16; ks++) {
                uint32_t a[4];
                ldA_x4(a, Es, 2056, mrow2, it * 256 + ks * 16, lane);
                uint32_t b0[2], b1[2];
                ldB_pair(b0, b1, Vb, 72, ks * 16, nbase, lane);
                mma_f16(acc, a, nsel ? b1 : b0);
            }
            __syncthreads();
        }

        int r0 = t0 + mrow2 + lr;
        int cb = h * DK + ncol + 2 * lc;
        *(__half2*)(Cc + (size_t)(b * Tt + r0) * Hh + cb) =
            __floats2half2_rn(acc[0], acc[1]);
        *(__half2*)(Cc + (size_t)(b * Tt + r0 + 8) * Hh + cb) =
            __floats2half2_rn(acc[2], acc[3]);
    }
}

// ============================================================
__global__ void mean_kernel(const __half* __restrict__ P, float* __restrict__ out)
{
    const size_t TS = (size_t)Tt * Ss;
    size_t idx = (size_t)blockIdx.x * blockDim.x + threadIdx.x;
    size_t base = idx * 8;
    if (base >= (size_t)Bb * TS) return;
    size_t b = base / TS, r = base - b * TS;
    float s[8] = {0,0,0,0,0,0,0,0};
    #pragma unroll
    for (int h = 0; h < NH; h++) {
        uint4 v = *(const uint4*)(P + ((size_t)(b * NH + h)) * TS + r);
        const __half2* hp = (const __half2*)&v;
        #pragma unroll
        for (int j = 0; j < 4; j++) {
            float2 f = __half22float2(hp[j]);
            s[2*j] += f.x; s[2*j+1] += f.y;
        }
    }
    float4 o0 = make_float4(s[0]*0.0625f, s[1]*0.0625f, s[2]*0.0625f, s[3]*0.0625f);
    float4 o1 = make_float4(s[4]*0.0625f, s[5]*0.0625f, s[6]*0.0625f, s[7]*0.0625f);
    *(float4*)(out + base) = o0;
    *(float4*)(out + base + 4) = o1;
}

// ============================================================
extern "C" void kernel_launch(void* const* d_in, const int* in_sizes, int n_in,
                              void* d_out, int out_size)
{
    const float* hiddens = (const float*)d_in[0];
    const float* qh      = (const float*)d_in[1];
    const int*   mask    = (const int*)  d_in[2];
    const float* W_q     = (const float*)d_in[3];
    const float* b_q     = (const float*)d_in[4];
    const float* W_k     = (const float*)d_in[5];
    const float* W_v     = (const float*)d_in[6];
    const float* W_o     = (const float*)d_in[7];
    const float* b_o     = (const float*)d_in[8];
    float* out = (float*)d_out;

    __half *pH, *pQH, *pWq, *pWk, *pWv, *pWo, *pQ, *pK, *pV, *pP, *pC;
    cudaGetSymbolAddress((void**)&pH,  g_H);
    cudaGetSymbolAddress((void**)&pQH, g_QH);
    cudaGetSymbolAddress((void**)&pWq, g_Wq);
    cudaGetSymbolAddress((void**)&pWk, g_Wk);
    cudaGetSymbolAddress((void**)&pWv, g_Wv);
    cudaGetSymbolAddress((void**)&pWo, g_Wo);
    cudaGetSymbolAddress((void**)&pQ,  g_Q);
    cudaGetSymbolAddress((void**)&pK,  g_K);
    cudaGetSymbolAddress((void**)&pV,  g_V);
    cudaGetSymbolAddress((void**)&pP,  g_P);
    cudaGetSymbolAddress((void**)&pC,  g_C);

    const int GEMM_SMEM = (2*128*72 + 2*64*136) * 2;
    const int KV_SMEM   = (2*128*72 + 4*64*136) * 2;
    const int SS_SMEM   = (32*2056 + 2*256*72 + 32*72) * 2;
    cudaFuncSetAttribute(gemm16<true , true >, cudaFuncAttributeMaxDynamicSharedMemorySize, GEMM_SMEM);
    cudaFuncSetAttribute(gemm16<false, true >, cudaFuncAttributeMaxDynamicSharedMemorySize, GEMM_SMEM);
    cudaFuncSetAttribute(kvgemm16, cudaFuncAttributeMaxDynamicSharedMemorySize, KV_SMEM);
    cudaFuncSetAttribute(scores_softmax_av, cudaFuncAttributeMaxDynamicSharedMemorySize, SS_SMEM);

    // fp32 -> fp16 converts
    f2h4<<<(Bb*Ss*Hh/4 + 255)/256, 256>>>(hiddens, pH,  Bb*Ss*Hh/4);
    f2h4<<<(Bb*Tt*Hh/4 + 255)/256, 256>>>(qh,      pQH, Bb*Tt*Hh/4);
    f2h4<<<(Hh*Hh/4 + 255)/256, 256>>>(W_q, pWq, Hh*Hh/4);
    f2h4<<<(Hh*Hh/4 + 255)/256, 256>>>(W_k, pWk, Hh*Hh/4);
    f2h4<<<(Hh*Hh/4 + 255)/256, 256>>>(W_v, pWv, Hh*Hh/4);
    f2h4<<<(Hh*Hh/4 + 255)/256, 256>>>(W_o, pWo, Hh*Hh/4);

    // Projections: Q (scaled), fused K+V
    gemm16<true , true ><<<dim3(8, 32), 256, GEMM_SMEM>>>(pQH, pWq, b_q, pQ, Bb*Tt, Hh, Hh, 0.125f);
    kvgemm16<<<dim3(8, 128), 256, KV_SMEM>>>(pH, pWk, pWv, pK, pV);

    // Fused scores + softmax + AV
    scores_softmax_av<<<dim3(Tt/32, Bb*NH), 512, SS_SMEM>>>(pQ, pK, pV, mask, pP, pC);

    // Head-mean
    {
        size_t n8 = (size_t)Bb * Tt * Ss / 8;
        mean_kernel<<<(unsigned)((n8 + 255) / 256), 256>>>(pP, out + (size_t)Bb*Tt*Hh);
    }

    // Output projection
    gemm16<false, true ><<<dim3(8, 32), 256, GEMM_SMEM>>>(pC, pWo, b_o, out, Bb*Tt, Hh, Hh, 1.0f);
}

// round 11
// speedup vs baseline: 1.1034x; 1.1034x over previous
#include <cuda_runtime.h>
#include <cuda_fp16.h>
#include <math.h>
#include <stdint.h>

#define Bb 8
#define Ss 2048
#define Tt 512
#define Hh 1024
#define NH 16
#define DK 64

// ---- scratch ----
__device__ __half g_H [(size_t)Bb*Ss*Hh];
__device__ __half g_QH[(size_t)Bb*Tt*Hh];
__device__ __half g_Wq[Hh*Hh], g_Wk[Hh*Hh], g_Wv[Hh*Hh], g_Wo[Hh*Hh];
__device__ __half g_Q [(size_t)Bb*Tt*Hh];
__device__ __half g_K [(size_t)Bb*Ss*Hh];
__device__ __half g_V [(size_t)Bb*Ss*Hh];
__device__ __half g_P [(size_t)Bb*NH*Tt*Ss];
__device__ __half g_C [(size_t)Bb*Tt*Hh];

// ------------------------------------------------------------
__device__ __forceinline__ uint32_t h2u(__half2 v) { return *(uint32_t*)&v; }

__device__ __forceinline__ void mma_f16(float* c, const uint32_t* a, const uint32_t* b) {
    asm volatile(
        "mma.sync.aligned.m16n8k16.row.col.f32.f16.f16.f32 "
        "{%0,%1,%2,%3}, {%4,%5,%6,%7}, {%8,%9}, {%0,%1,%2,%3};"
        : "+f"(c[0]), "+f"(c[1]), "+f"(c[2]), "+f"(c[3])
        : "r"(a[0]), "r"(a[1]), "r"(a[2]), "r"(a[3]),
          "r"(b[0]), "r"(b[1]));
}

__device__ __forceinline__ void cpa16(void* dst, const void* src) {
    uint32_t d = (uint32_t)__cvta_generic_to_shared(dst);
    asm volatile("cp.async.cg.shared.global [%0], [%1], 16;" :: "r"(d), "l"(src));
}
__device__ __forceinline__ void cp_commit() { asm volatile("cp.async.commit_group;"); }
template<int N_> __device__ __forceinline__ void cp_wait() {
    asm volatile("cp.async.wait_group %0;" :: "n"(N_));
}

__device__ __forceinline__ void ldsm_x4(uint32_t* r, uint32_t addr) {
    asm volatile("ldmatrix.sync.aligned.m8n8.x4.shared.b16 {%0,%1,%2,%3}, [%4];"
        : "=r"(r[0]), "=r"(r[1]), "=r"(r[2]), "=r"(r[3]) : "r"(addr));
}
__device__ __forceinline__ void ldsm_x4_t(uint32_t* r, uint32_t addr) {
    asm volatile("ldmatrix.sync.aligned.m8n8.x4.trans.shared.b16 {%0,%1,%2,%3}, [%4];"
        : "=r"(r[0]), "=r"(r[1]), "=r"(r[2]), "=r"(r[3]) : "r"(addr));
}

__device__ __forceinline__ void ldA_x4(uint32_t* r, const __half* S, int LD,
                                       int row0, int col0, int lane) {
    int g = lane >> 3, rr = lane & 7;
    const __half* p = S + (size_t)(row0 + (g & 1) * 8 + rr) * LD + col0 + (g >> 1) * 8;
    ldsm_x4(r, (uint32_t)__cvta_generic_to_shared(p));
}
__device__ __forceinline__ void ldBn_x4(uint32_t* b0, uint32_t* b1,
                                        const __half* S, int LD, int n0, int k0, int lane) {
    int g = lane >> 3, rr = lane & 7;
    const __half* p = S + (n0 + (g & 1) * 8 + rr) * LD + k0 + (g >> 1) * 8;
    uint32_t q[4];
    ldsm_x4(q, (uint32_t)__cvta_generic_to_shared(p));
    b0[0] = q[0]; b0[1] = q[2];
    b1[0] = q[1]; b1[1] = q[3];
}
__device__ __forceinline__ void ldB_pair(uint32_t* b0, uint32_t* b1,
                                         const __half* S, int RS, int k0, int n0, int lane) {
    int g = lane >> 3, r = lane & 7;
    int row = k0 + r + (g & 1) * 8;
    int col = n0 + (g >> 1) * 8;
    uint32_t q[4];
    ldsm_x4_t(q, (uint32_t)__cvta_generic_to_shared(S + row * RS + col));
    b0[0] = q[0]; b0[1] = q[1];
    b1[0] = q[2]; b1[1] = q[3];
}

// ============================================================
__global__ void f2h4(const float* __restrict__ in, __half* __restrict__ out, int n4) {
    int i = blockIdx.x * blockDim.x + threadIdx.x;
    if (i < n4) {
        float4 v = ((const float4*)in)[i];
        uint2 u;
        u.x = h2u(__floats2half2_rn(v.x, v.y));
        u.y = h2u(__floats2half2_rn(v.z, v.w));
        ((uint2*)out)[i] = u;
    }
}

// ============================================================
// fp16 GEMM: 128x128 tile, BK=64, cp.async dbl-buf, 8 warps 64x32.
// ============================================================
template<bool F16OUT, bool HAS_BIAS>
__global__ void __launch_bounds__(256) gemm16(
    const __half* __restrict__ A, const __half* __restrict__ W,
    const float* __restrict__ bias, void* __restrict__ Cout,
    int M, int N, int K, float scale)
{
    extern __shared__ __half smx[];
    __half* As = smx;                  // 2 x [128][72]
    __half* Bs = smx + 2 * 128 * 72;   // 2 x [64][136]
    int tid = threadIdx.x, lane = tid & 31, wid = tid >> 5;
    int lr = lane >> 2, lc = lane & 3;
    int wm = (wid >> 2) * 64, wn = (wid & 3) * 32;
    int bx = blockIdx.x, by = blockIdx.y;

    const __half* Ag = A + (size_t)by * 128 * K;
    const __half* Wg = W + bx * 128;

    float acc[4][4][4];
    #pragma unroll
    for (int i = 0; i < 4; i++)
        #pragma unroll
        for (int j = 0; j < 4; j++)
            #pragma unroll
            for (int q = 0; q < 4; q++) acc[i][j][q] = 0.f;

    auto loadAB = [&](int buf, int k0) {
        __half* Ab = As + buf * 128 * 72;
        __half* Bb2 = Bs + buf * 64 * 136;
        #pragma unroll
        for (int j = 0; j < 4; j++) {
            int id = tid + j * 256;
            int r = id >> 3, c = (id & 7) * 8;
            cpa16(Ab + r * 72 + c, Ag + (size_t)r * K + k0 + c);
        }
        #pragma unroll
        for (int j = 0; j < 4; j++) {
            int id = tid + j * 256;
            int r = id >> 4, c = (id & 15) * 8;
            cpa16(Bb2 + r * 136 + c, Wg + (size_t)(k0 + r) * N + c);
        }
        cp_commit();
    };

    int nit = K / 64;
    loadAB(0, 0);
    for (int it = 0; it < nit; it++) {
        if (it + 1 < nit) loadAB((it + 1) & 1, (it + 1) * 64);
        if (it + 1 < nit) cp_wait<1>(); else cp_wait<0>();
        __syncthreads();
        const __half* Ab = As + (it & 1) * 128 * 72;
        const __half* Bb2 = Bs + (it & 1) * 64 * 136;
        #pragma unroll
        for (int ks = 0; ks < 64; ks += 16) {
            uint32_t a[4][4], b[4][2];
            #pragma unroll
            for (int im = 0; im < 4; im++)
                ldA_x4(a[im], Ab, 72, wm + im * 16, ks, lane);
            ldB_pair(b[0], b[1], Bb2, 136, ks, wn,      lane);
            ldB_pair(b[2], b[3], Bb2, 136, ks, wn + 16, lane);
            #pragma unroll
            for (int im = 0; im < 4; im++)
                #pragma unroll
                for (int in_ = 0; in_ < 4; in_++)
                    mma_f16(acc[im][in_], a[im], b[in_]);
        }
        __syncthreads();
    }

    #pragma unroll
    for (int im = 0; im < 4; im++) {
        #pragma unroll
        for (int in_ = 0; in_ < 4; in_++) {
            int r0 = by * 128 + wm + im * 16 + lr;
            int cb = bx * 128 + wn + in_ * 8 + 2 * lc;
            float b0 = HAS_BIAS ? bias[cb] : 0.f;
            float b1 = HAS_BIAS ? bias[cb + 1] : 0.f;
            float x0 = (acc[im][in_][0] + b0) * scale;
            float x1 = (acc[im][in_][1] + b1) * scale;
            float x2 = (acc[im][in_][2] + b0) * scale;
            float x3 = (acc[im][in_][3] + b1) * scale;
            if (F16OUT) {
                __half* C = (__half*)Cout;
                *(__half2*)(C + (size_t)r0 * N + cb)       = __floats2half2_rn(x0, x1);
                *(__half2*)(C + (size_t)(r0 + 8) * N + cb) = __floats2half2_rn(x2, x3);
            } else {
                float* C = (float*)Cout;
                *(float2*)(C + (size_t)r0 * N + cb)       = make_float2(x0, x1);
                *(float2*)(C + (size_t)(r0 + 8) * N + cb) = make_float2(x2, x3);
            }
        }
    }
}

// ============================================================
// Fused K+V projection (legacy HMMA)
// ============================================================
__global__ void __launch_bounds__(256, 1) kvgemm16(
    const __half* __restrict__ A, const __half* __restrict__ Wk,
    const __half* __restrict__ Wv, __half* __restrict__ Ko,
    __half* __restrict__ Vo)
{
    const int N = Hh, K = Hh;
    extern __shared__ __half smk[];
    __half* As  = smk;                    // 2 x [128][72]
    __half* Bks = smk + 2 * 128 * 72;     // 2 x [64][136]
    __half* Bvs = Bks + 2 * 64 * 136;     // 2 x [64][136]
    int tid = threadIdx.x, lane = tid & 31, wid = tid >> 5;
    int lr = lane >> 2, lc = lane & 3;
    int wm = (wid >> 2) * 64, wn = (wid & 3) * 32;
    int bx = blockIdx.x, by = blockIdx.y;

    const __half* Ag  = A  + (size_t)by * 128 * K;
    const __half* Wkg = Wk + bx * 128;
    const __half* Wvg = Wv + bx * 128;

    float accK[4][4][4], accV[4][4][4];
    #pragma unroll
    for (int i = 0; i < 4; i++)
        #pragma unroll
        for (int j = 0; j < 4; j++)
            #pragma unroll
            for (int q = 0; q < 4; q++) { accK[i][j][q] = 0.f; accV[i][j][q] = 0.f; }

    auto loadAB = [&](int buf, int k0) {
        __half* Ab  = As  + buf * 128 * 72;
        __half* Bkb = Bks + buf * 64 * 136;
        __half* Bvb = Bvs + buf * 64 * 136;
        #pragma unroll
        for (int j = 0; j < 4; j++) {
            int id = tid + j * 256;
            int r = id >> 3, c = (id & 7) * 8;
            cpa16(Ab + r * 72 + c, Ag + (size_t)r * K + k0 + c);
        }
        #pragma unroll
        for (int j = 0; j < 4; j++) {
            int id = tid + j * 256;
            int r = id >> 4, c = (id & 15) * 8;
            cpa16(Bkb + r * 136 + c, Wkg + (size_t)(k0 + r) * N + c);
            cpa16(Bvb + r * 136 + c, Wvg + (size_t)(k0 + r) * N + c);
        }
        cp_commit();
    };

    const int nit = K / 64;
    loadAB(0, 0);
    for (int it = 0; it < nit; it++) {
        if (it + 1 < nit) loadAB((it + 1) & 1, (it + 1) * 64);
        if (it + 1 < nit) cp_wait<1>(); else cp_wait<0>();
        __syncthreads();
        const __half* Ab  = As  + (it & 1) * 128 * 72;
        const __half* Bkb = Bks + (it & 1) * 64 * 136;
        const __half* Bvb = Bvs + (it & 1) * 64 * 136;
        #pragma unroll
        for (int ks = 0; ks < 64; ks += 16) {
            uint32_t a[4][4], bk[4][2], bv[4][2];
            #pragma unroll
            for (int im = 0; im < 4; im++)
                ldA_x4(a[im], Ab, 72, wm + im * 16, ks, lane);
            ldB_pair(bk[0], bk[1], Bkb, 136, ks, wn,      lane);
            ldB_pair(bk[2], bk[3], Bkb, 136, ks, wn + 16, lane);
            ldB_pair(bv[0], bv[1], Bvb, 136, ks, wn,      lane);
            ldB_pair(bv[2], bv[3], Bvb, 136, ks, wn + 16, lane);
            #pragma unroll
            for (int im = 0; im < 4; im++)
                #pragma unroll
                for (int in_ = 0; in_ < 4; in_++) {
                    mma_f16(accK[im][in_], a[im], bk[in_]);
                    mma_f16(accV[im][in_], a[im], bv[in_]);
                }
        }
        __syncthreads();
    }

    #pragma unroll
    for (int im = 0; im < 4; im++) {
        #pragma unroll
        for (int in_ = 0; in_ < 4; in_++) {
            int r0 = by * 128 + wm + im * 16 + lr;
            int cb = bx * 128 + wn + in_ * 8 + 2 * lc;
            *(__half2*)(Ko + (size_t)r0 * N + cb) =
                __floats2half2_rn(accK[im][in_][0], accK[im][in_][1]);
            *(__half2*)(Ko + (size_t)(r0 + 8) * N + cb) =
                __floats2half2_rn(accK[im][in_][2], accK[im][in_][3]);
            *(__half2*)(Vo + (size_t)r0 * N + cb) =
                __floats2half2_rn(accV[im][in_][0], accV[im][in_][1]);
            *(__half2*)(Vo + (size_t)(r0 + 8) * N + cb) =
                __floats2half2_rn(accV[im][in_][2], accV[im][in_][3]);
        }
    }
}

// ============================================================
// Fused scores + softmax: 256 threads, 16 t-rows, s-chunk 128.
// 102.5 KB smem -> 2 CTAs/SM so tensor phase of one CTA overlaps
// the MUFU/LSU softmax phase of the other.
// ============================================================
__global__ void __launch_bounds__(256) scores_softmax(
    const __half* __restrict__ Q, const __half* __restrict__ Kg,
    const int* __restrict__ mask, __half* __restrict__ P)
{
    extern __shared__ __half sms[];
    __half* Es = sms;                 // [16][2056]
    __half* Ks = sms + 16 * 2056;     // 2 x [128][72]
    __half* Qs = Ks + 2 * 128 * 72;   // [16][72]

    int tid = threadIdx.x, lane = tid & 31, wid = tid >> 5;   // wid 0..7
    int lr = lane >> 2, lc = lane & 3;
    int bh = blockIdx.y, b = bh >> 4, h = bh & 15;
    int t0 = blockIdx.x * 16;
    int n0 = wid * 16;

    if (tid < 128) {
        int r = tid >> 3, c = (tid & 7) * 8;
        *(uint4*)&Qs[r * 72 + c] =
            *(const uint4*)(Q + (size_t)(b * Tt + t0 + r) * Hh + h * DK + c);
    }

    auto loadK = [&](int buf, int s0) {
        __half* Kb = Ks + buf * 128 * 72;
        #pragma unroll
        for (int j = 0; j < 4; j++) {
            int id = tid + j * 256;
            int r = id >> 3, c = (id & 7) * 8;
            cpa16(Kb + r * 72 + c, Kg + (size_t)(b * Ss + s0 + r) * Hh + h * DK + c);
        }
        cp_commit();
    };

    loadK(0, 0);
    __syncthreads();

    // Hoist Q fragments: 1 m-frag x 4 k-steps
    uint32_t qa[4][4];
    #pragma unroll
    for (int kk = 0; kk < 4; kk++)
        ldA_x4(qa[kk], Qs, 72, 0, kk * 16, lane);

    for (int it = 0; it < 16; it++) {
        if (it + 1 < 16) loadK((it + 1) & 1, (it + 1) * 128);
        if (it + 1 < 16) cp_wait<1>(); else cp_wait<0>();
        __syncthreads();
        const __half* Kb = Ks + (it & 1) * 128 * 72;
        int s0 = it * 128;

        float acc[2][4];
        #pragma unroll
        for (int j = 0; j < 2; j++)
            #pragma unroll
            for (int q = 0; q < 4; q++) acc[j][q] = 0.f;

        #pragma unroll
        for (int kk = 0; kk < 4; kk++) {
            uint32_t bf[2][2];
            ldBn_x4(bf[0], bf[1], Kb, 72, n0, kk * 16, lane);
            mma_f16(acc[0], qa[kk], bf[0]);
            mma_f16(acc[1], qa[kk], bf[1]);
        }

        #pragma unroll
        for (int in_ = 0; in_ < 2; in_++) {
            int s = s0 + n0 + in_ * 8 + 2 * lc;
            *(__half2*)&Es[lr * 2056 + s] =
                __floats2half2_rn(acc[in_][0], acc[in_][1]);
            *(__half2*)&Es[(lr + 8) * 2056 + s] =
                __floats2half2_rn(acc[in_][2], acc[in_][3]);
        }
        __syncthreads();
    }

    // ---- softmax: 8 warps x 2 rows ----
    const int* mrow = mask + b * Ss;
    const __half minus3e4 = __float2half(-30000.f);
    #pragma unroll
    for (int rr = 0; rr < 2; rr++) {
        int r = wid * 2 + rr;
        uint4 E[8];
        float mx = -3.0e38f;
        #pragma unroll
        for (int i = 0; i < 8; i++) {
            int s = i * 256 + lane * 8;
            E[i] = *(uint4*)&Es[r * 2056 + s];
            int4 m0 = *(const int4*)&mrow[s];
            int4 m1 = *(const int4*)&mrow[s + 4];
            __half* hp = (__half*)&E[i];
            if (!m0.x) hp[0] = minus3e4;
            if (!m0.y) hp[1] = minus3e4;
            if (!m0.z) hp[2] = minus3e4;
            if (!m0.w) hp[3] = minus3e4;
            if (!m1.x) hp[4] = minus3e4;
            if (!m1.y) hp[5] = minus3e4;
            if (!m1.z) hp[6] = minus3e4;
            if (!m1.w) hp[7] = minus3e4;
            __half2* h2p = (__half2*)&E[i];
            #pragma unroll
            for (int j = 0; j < 4; j++) {
                float2 f = __half22float2(h2p[j]);
                mx = fmaxf(mx, fmaxf(f.x, f.y));
            }
        }
        #pragma unroll
        for (int o = 16; o; o >>= 1) mx = fmaxf(mx, __shfl_xor_sync(0xffffffffu, mx, o));

        float sum = 0.f;
        #pragma unroll
        for (int i = 0; i < 8; i++) {
            __half2* h2p = (__half2*)&E[i];
            #pragma unroll
            for (int j = 0; j < 4; j++) {
                float2 f = __half22float2(h2p[j]);
                float e0 = __expf(f.x - mx), e1 = __expf(f.y - mx);
                sum += e0 + e1;
                h2p[j] = __floats2half2_rn(e0, e1);
            }
        }
        #pragma unroll
        for (int o = 16; o; o >>= 1) sum += __shfl_xor_sync(0xffffffffu, sum, o);
        float inv = 1.0f / sum;

        __half* Pd = P + ((size_t)bh * Tt + t0 + r) * Ss;
        #pragma unroll
        for (int i = 0; i < 8; i++) {
            __half2* h2p = (__half2*)&E[i];
            #pragma unroll
            for (int j = 0; j < 4; j++) {
                float2 f = __half22float2(h2p[j]);
                h2p[j] = __floats2half2_rn(f.x * inv, f.y * inv);
            }
            int s = i * 256 + lane * 8;
            *(uint4*)(Pd + s) = E[i];
        }
    }
}

// ============================================================
// mean over heads
// ============================================================
__global__ void mean_kernel(const __half* __restrict__ P, float* __restrict__ out)
{
    const size_t TS = (size_t)Tt * Ss;
    size_t idx = (size_t)blockIdx.x * blockDim.x + threadIdx.x;
    size_t base = idx * 8;
    if (base >= (size_t)Bb * TS) return;
    size_t b = base / TS, r = base - b * TS;
    float s[8] = {0,0,0,0,0,0,0,0};
    #pragma unroll
    for (int h = 0; h < NH; h++) {
        uint4 v = *(const uint4*)(P + ((size_t)(b * NH + h)) * TS + r);
        const __half2* hp = (const __half2*)&v;
        #pragma unroll
        for (int j = 0; j < 4; j++) {
            float2 f = __half22float2(hp[j]);
            s[2*j] += f.x; s[2*j+1] += f.y;
        }
    }
    float4 o0 = make_float4(s[0]*0.0625f, s[1]*0.0625f, s[2]*0.0625f, s[3]*0.0625f);
    float4 o1 = make_float4(s[4]*0.0625f, s[5]*0.0625f, s[6]*0.0625f, s[7]*0.0625f);
    *(float4*)(out + base) = o0;
    *(float4*)(out + base + 4) = o1;
}

// ============================================================
// AV: cp.async double-buffered, ldmatrix P fragments.
// ============================================================
__global__ void __launch_bounds__(256) av_f16(
    const __half* __restrict__ P, const __half* __restrict__ V,
    __half* __restrict__ Cc)
{
    __shared__ __half Ps[2*128*72];
    __shared__ __half Vs[2*64*72];
    int tid = threadIdx.x, lane = tid & 31, wid = tid >> 5;
    int lr = lane >> 2, lc = lane & 3;
    int wm = (wid >> 1) * 32, wn = (wid & 1) * 32;
    int bh = blockIdx.y, b = bh >> 4, h = bh & 15;
    int t0 = blockIdx.x * 128;

    float acc[2][4][4];
    #pragma unroll
    for (int i = 0; i < 2; i++)
        #pragma unroll
        for (int j = 0; j < 4; j++)
            #pragma unroll
            for (int q = 0; q < 4; q++) acc[i][j][q] = 0.f;

    const __half* Pbase = P + ((size_t)bh * Tt + t0) * Ss;
    const __half* Vbase = V + (size_t)b * Ss * Hh + h * DK;

    auto loadPV = [&](int buf, int s0) {
        __half* Pb = Ps + buf * 128 * 72;
        __half* Vb = Vs + buf * 64 * 72;
        #pragma unroll
        for (int j = 0; j < 4; j++) {
            int id = tid + j * 256;
            int r = id >> 3, c = (id & 7) * 8;
            cpa16(Pb + r * 72 + c, Pbase + (size_t)r * Ss + s0 + c);
        }
        #pragma unroll
        for (int j = 0; j < 2; j++) {
            int id = tid + j * 256;
            int r = id >> 3, c = (id & 7) * 8;
            cpa16(Vb + r * 72 + c, Vbase + (size_t)(s0 + r) * Hh + c);
        }
        cp_commit();
    };

    loadPV(0, 0);
    for (int it = 0; it < Ss / 64; it++) {
        if (it + 1 < Ss / 64) loadPV((it + 1) & 1, (it + 1) * 64);
        if (it + 1 < Ss / 64) cp_wait<1>(); else cp_wait<0>();
        __syncthreads();
        const __half* Pb = Ps + (it & 1) * 128 * 72;
        const __half* Vb = Vs + (it & 1) * 64 * 72;

        #pragma unroll
        for (int kk = 0; kk < 4; kk++) {
            uint32_t a[2][4], b2[4][2];
            #pragma unroll
            for (int im = 0; im < 2; im++)
                ldA_x4(a[im], Pb, 72, wm + im * 16, kk * 16, lane);
            ldB_pair(b2[0], b2[1], Vb, 72, kk * 16, wn,      lane);
            ldB_pair(b2[2], b2[3], Vb, 72, kk * 16, wn + 16, lane);
            #pragma unroll
            for (int im = 0; im < 2; im++)
                #pragma unroll
                for (int in_ = 0; in_ < 4; in_++)
                    mma_f16(acc[im][in_], a[im], b2[in_]);
        }
        __syncthreads();
    }

    #pragma unroll
    for (int im = 0; im < 2; im++) {
        #pragma unroll
        for (int in_ = 0; in_ < 4; in_++) {
            int r0 = t0 + wm + im * 16 + lr;
            int cb = wn + in_ * 8 + 2 * lc;
            *(__half2*)(Cc + (size_t)(b * Tt + r0) * Hh + h * DK + cb) =
                __floats2half2_rn(acc[im][in_][0], acc[im][in_][1]);
            *(__half2*)(Cc + (size_t)(b * Tt + r0 + 8) * Hh + h * DK + cb) =
                __floats2half2_rn(acc[im][in_][2], acc[im][in_][3]);
        }
    }
}

// ============================================================
extern "C" void kernel_launch(void* const* d_in, const int* in_sizes, int n_in,
                              void* d_out, int out_size)
{
    const float* hiddens = (const float*)d_in[0];
    const float* qh      = (const float*)d_in[1];
    const int*   mask    = (const int*)  d_in[2];
    const float* W_q     = (const float*)d_in[3];
    const float* b_q     = (const float*)d_in[4];
    const float* W_k     = (const float*)d_in[5];
    const float* W_v     = (const float*)d_in[6];
    const float* W_o     = (const float*)d_in[7];
    const float* b_o     = (const float*)d_in[8];
    float* out = (float*)d_out;

    __half *pH, *pQH, *pWq, *pWk, *pWv, *pWo, *pQ, *pK, *pV, *pP, *pC;
    cudaGetSymbolAddress((void**)&pH,  g_H);
    cudaGetSymbolAddress((void**)&pQH, g_QH);
    cudaGetSymbolAddress((void**)&pWq, g_Wq);
    cudaGetSymbolAddress((void**)&pWk, g_Wk);
    cudaGetSymbolAddress((void**)&pWv, g_Wv);
    cudaGetSymbolAddress((void**)&pWo, g_Wo);
    cudaGetSymbolAddress((void**)&pQ,  g_Q);
    cudaGetSymbolAddress((void**)&pK,  g_K);
    cudaGetSymbolAddress((void**)&pV,  g_V);
    cudaGetSymbolAddress((void**)&pP,  g_P);
    cudaGetSymbolAddress((void**)&pC,  g_C);

    const int GEMM_SMEM = (2*128*72 + 2*64*136) * 2;
    const int KV_SMEM   = (2*128*72 + 4*64*136) * 2;
    const int SS_SMEM   = (16*2056 + 2*128*72 + 16*72) * 2;
    cudaFuncSetAttribute(gemm16<true , true >, cudaFuncAttributeMaxDynamicSharedMemorySize, GEMM_SMEM);
    cudaFuncSetAttribute(gemm16<false, true >, cudaFuncAttributeMaxDynamicSharedMemorySize, GEMM_SMEM);
    cudaFuncSetAttribute(kvgemm16, cudaFuncAttributeMaxDynamicSharedMemorySize, KV_SMEM);
    cudaFuncSetAttribute(scores_softmax, cudaFuncAttributeMaxDynamicSharedMemorySize, SS_SMEM);

    // fp32 -> fp16 converts
    f2h4<<<(Bb*Ss*Hh/4 + 255)/256, 256>>>(hiddens, pH,  Bb*Ss*Hh/4);
    f2h4<<<(Bb*Tt*Hh/4 + 255)/256, 256>>>(qh,      pQH, Bb*Tt*Hh/4);
    f2h4<<<(Hh*Hh/4 + 255)/256, 256>>>(W_q, pWq, Hh*Hh/4);
    f2h4<<<(Hh*Hh/4 + 255)/256, 256>>>(W_k, pWk, Hh*Hh/4);
    f2h4<<<(Hh*Hh/4 + 255)/256, 256>>>(W_v, pWv, Hh*Hh/4);
    f2h4<<<(Hh*Hh/4 + 255)/256, 256>>>(W_o, pWo, Hh*Hh/4);

    // Projections: Q (scaled), fused K+V
    gemm16<true , true ><<<dim3(8, 32), 256, GEMM_SMEM>>>(pQH, pWq, b_q, pQ, Bb*Tt, Hh, Hh, 0.125f);
    kvgemm16<<<dim3(8, 128), 256, KV_SMEM>>>(pH, pWk, pWv, pK, pV);

    // Fused scores + softmax (16 t-rows per block, 2 CTAs/SM)
    scores_softmax<<<dim3(Tt/16, Bb*NH), 256, SS_SMEM>>>(pQ, pK, mask, pP);

    // Head-mean
    {
        size_t n8 = (size_t)Bb * Tt * Ss / 8;
        mean_kernel<<<(unsigned)((n8 + 255) / 256), 256>>>(pP, out + (size_t)Bb*Tt*Hh);
    }

    // AV and output projection
    av_f16<<<dim3(Tt/128, Bb*NH), 256>>>(pP, pV, pC);
    gemm16<false, true ><<<dim3(8, 32), 256, GEMM_SMEM>>>(pC, pWo, b_o, out, Bb*Tt, Hh, Hh, 1.0f);
}

// round 12
// speedup vs baseline: 1.1481x; 1.0405x over previous
#include <cuda_runtime.h>
#include <cuda_fp16.h>
#include <math.h>
#include <stdint.h>

#define Bb 8
#define Ss 2048
#define Tt 512
#define Hh 1024
#define NH 16
#define DK 64

// ---- scratch ----
__device__ __half g_H [(size_t)Bb*Ss*Hh];
__device__ __half g_QH[(size_t)Bb*Tt*Hh];
__device__ __half g_Wq[Hh*Hh], g_Wk[Hh*Hh], g_Wv[Hh*Hh], g_Wo[Hh*Hh];
__device__ __half g_Q [(size_t)Bb*Tt*Hh];
__device__ __half g_K [(size_t)Bb*Ss*Hh];
__device__ __half g_V [(size_t)Bb*Ss*Hh];
__device__ __half g_P [(size_t)Bb*NH*Tt*Ss];
__device__ __half g_C [(size_t)Bb*Tt*Hh];

// ------------------------------------------------------------
__device__ __forceinline__ uint32_t h2u(__half2 v) { return *(uint32_t*)&v; }

__device__ __forceinline__ void mma_f16(float* c, const uint32_t* a, const uint32_t* b) {
    asm volatile(
        "mma.sync.aligned.m16n8k16.row.col.f32.f16.f16.f32 "
        "{%0,%1,%2,%3}, {%4,%5,%6,%7}, {%8,%9}, {%0,%1,%2,%3};"
        : "+f"(c[0]), "+f"(c[1]), "+f"(c[2]), "+f"(c[3])
        : "r"(a[0]), "r"(a[1]), "r"(a[2]), "r"(a[3]),
          "r"(b[0]), "r"(b[1]));
}

__device__ __forceinline__ void cpa16(void* dst, const void* src) {
    uint32_t d = (uint32_t)__cvta_generic_to_shared(dst);
    asm volatile("cp.async.cg.shared.global [%0], [%1], 16;" :: "r"(d), "l"(src));
}
__device__ __forceinline__ void cp_commit() { asm volatile("cp.async.commit_group;"); }
template<int N_> __device__ __forceinline__ void cp_wait() {
    asm volatile("cp.async.wait_group %0;" :: "n"(N_));
}

__device__ __forceinline__ void ldsm_x4(uint32_t* r, uint32_t addr) {
    asm volatile("ldmatrix.sync.aligned.m8n8.x4.shared.b16 {%0,%1,%2,%3}, [%4];"
        : "=r"(r[0]), "=r"(r[1]), "=r"(r[2]), "=r"(r[3]) : "r"(addr));
}
__device__ __forceinline__ void ldsm_x4_t(uint32_t* r, uint32_t addr) {
    asm volatile("ldmatrix.sync.aligned.m8n8.x4.trans.shared.b16 {%0,%1,%2,%3}, [%4];"
        : "=r"(r[0]), "=r"(r[1]), "=r"(r[2]), "=r"(r[3]) : "r"(addr));
}

__device__ __forceinline__ void ldA_x4(uint32_t* r, const __half* S, int LD,
                                       int row0, int col0, int lane) {
    int g = lane >> 3, rr = lane & 7;
    const __half* p = S + (size_t)(row0 + (g & 1) * 8 + rr) * LD + col0 + (g >> 1) * 8;
    ldsm_x4(r, (uint32_t)__cvta_generic_to_shared(p));
}
__device__ __forceinline__ void ldBn_x4(uint32_t* b0, uint32_t* b1,
                                        const __half* S, int LD, int n0, int k0, int lane) {
    int g = lane >> 3, rr = lane & 7;
    const __half* p = S + (n0 + (g & 1) * 8 + rr) * LD + k0 + (g >> 1) * 8;
    uint32_t q[4];
    ldsm_x4(q, (uint32_t)__cvta_generic_to_shared(p));
    b0[0] = q[0]; b0[1] = q[2];
    b1[0] = q[1]; b1[1] = q[3];
}
__device__ __forceinline__ void ldB_pair(uint32_t* b0, uint32_t* b1,
                                         const __half* S, int RS, int k0, int n0, int lane) {
    int g = lane >> 3, r = lane & 7;
    int row = k0 + r + (g & 1) * 8;
    int col = n0 + (g >> 1) * 8;
    uint32_t q[4];
    ldsm_x4_t(q, (uint32_t)__cvta_generic_to_shared(S + row * RS + col));
    b0[0] = q[0]; b0[1] = q[1];
    b1[0] = q[2]; b1[1] = q[3];
}

// ============================================================
__global__ void f2h4(const float* __restrict__ in, __half* __restrict__ out, int n4) {
    int i = blockIdx.x * blockDim.x + threadIdx.x;
    if (i < n4) {
        float4 v = ((const float4*)in)[i];
        uint2 u;
        u.x = h2u(__floats2half2_rn(v.x, v.y));
        u.y = h2u(__floats2half2_rn(v.z, v.w));
        ((uint2*)out)[i] = u;
    }
}

// ============================================================
// fp16 GEMM: 128x128 tile, BK=64, cp.async dbl-buf, 8 warps 64x32.
// ============================================================
template<bool F16OUT, bool HAS_BIAS>
__global__ void __launch_bounds__(256) gemm16(
    const __half* __restrict__ A, const __half* __restrict__ W,
    const float* __restrict__ bias, void* __restrict__ Cout,
    int M, int N, int K, float scale)
{
    extern __shared__ __half smx[];
    __half* As = smx;                  // 2 x [128][72]
    __half* Bs = smx + 2 * 128 * 72;   // 2 x [64][136]
    int tid = threadIdx.x, lane = tid & 31, wid = tid >> 5;
    int lr = lane >> 2, lc = lane & 3;
    int wm = (wid >> 2) * 64, wn = (wid & 3) * 32;
    int bx = blockIdx.x, by = blockIdx.y;

    const __half* Ag = A + (size_t)by * 128 * K;
    const __half* Wg = W + bx * 128;

    float acc[4][4][4];
    #pragma unroll
    for (int i = 0; i < 4; i++)
        #pragma unroll
        for (int j = 0; j < 4; j++)
            #pragma unroll
            for (int q = 0; q < 4; q++) acc[i][j][q] = 0.f;

    auto loadAB = [&](int buf, int k0) {
        __half* Ab = As + buf * 128 * 72;
        __half* Bb2 = Bs + buf * 64 * 136;
        #pragma unroll
        for (int j = 0; j < 4; j++) {
            int id = tid + j * 256;
            int r = id >> 3, c = (id & 7) * 8;
            cpa16(Ab + r * 72 + c, Ag + (size_t)r * K + k0 + c);
        }
        #pragma unroll
        for (int j = 0; j < 4; j++) {
            int id = tid + j * 256;
            int r = id >> 4, c = (id & 15) * 8;
            cpa16(Bb2 + r * 136 + c, Wg + (size_t)(k0 + r) * N + c);
        }
        cp_commit();
    };

    int nit = K / 64;
    loadAB(0, 0);
    for (int it = 0; it < nit; it++) {
        if (it + 1 < nit) loadAB((it + 1) & 1, (it + 1) * 64);
        if (it + 1 < nit) cp_wait<1>(); else cp_wait<0>();
        __syncthreads();
        const __half* Ab = As + (it & 1) * 128 * 72;
        const __half* Bb2 = Bs + (it & 1) * 64 * 136;
        #pragma unroll
        for (int ks = 0; ks < 64; ks += 16) {
            uint32_t a[4][4], b[4][2];
            #pragma unroll
            for (int im = 0; im < 4; im++)
                ldA_x4(a[im], Ab, 72, wm + im * 16, ks, lane);
            ldB_pair(b[0], b[1], Bb2, 136, ks, wn,      lane);
            ldB_pair(b[2], b[3], Bb2, 136, ks, wn + 16, lane);
            #pragma unroll
            for (int im = 0; im < 4; im++)
                #pragma unroll
                for (int in_ = 0; in_ < 4; in_++)
                    mma_f16(acc[im][in_], a[im], b[in_]);
        }
        __syncthreads();
    }

    #pragma unroll
    for (int im = 0; im < 4; im++) {
        #pragma unroll
        for (int in_ = 0; in_ < 4; in_++) {
            int r0 = by * 128 + wm + im * 16 + lr;
            int cb = bx * 128 + wn + in_ * 8 + 2 * lc;
            float b0 = HAS_BIAS ? bias[cb] : 0.f;
            float b1 = HAS_BIAS ? bias[cb + 1] : 0.f;
            float x0 = (acc[im][in_][0] + b0) * scale;
            float x1 = (acc[im][in_][1] + b1) * scale;
            float x2 = (acc[im][in_][2] + b0) * scale;
            float x3 = (acc[im][in_][3] + b1) * scale;
            if (F16OUT) {
                __half* C = (__half*)Cout;
                *(__half2*)(C + (size_t)r0 * N + cb)       = __floats2half2_rn(x0, x1);
                *(__half2*)(C + (size_t)(r0 + 8) * N + cb) = __floats2half2_rn(x2, x3);
            } else {
                float* C = (float*)Cout;
                *(float2*)(C + (size_t)r0 * N + cb)       = make_float2(x0, x1);
                *(float2*)(C + (size_t)(r0 + 8) * N + cb) = make_float2(x2, x3);
            }
        }
    }
}

// ============================================================
// Fused K+V projection (legacy HMMA)
// ============================================================
__global__ void __launch_bounds__(256, 1) kvgemm16(
    const __half* __restrict__ A, const __half* __restrict__ Wk,
    const __half* __restrict__ Wv, __half* __restrict__ Ko,
    __half* __restrict__ Vo)
{
    const int N = Hh, K = Hh;
    extern __shared__ __half smk[];
    __half* As  = smk;                    // 2 x [128][72]
    __half* Bks = smk + 2 * 128 * 72;     // 2 x [64][136]
    __half* Bvs = Bks + 2 * 64 * 136;     // 2 x [64][136]
    int tid = threadIdx.x, lane = tid & 31, wid = tid >> 5;
    int lr = lane >> 2, lc = lane & 3;
    int wm = (wid >> 2) * 64, wn = (wid & 3) * 32;
    int bx = blockIdx.x, by = blockIdx.y;

    const __half* Ag  = A  + (size_t)by * 128 * K;
    const __half* Wkg = Wk + bx * 128;
    const __half* Wvg = Wv + bx * 128;

    float accK[4][4][4], accV[4][4][4];
    #pragma unroll
    for (int i = 0; i < 4; i++)
        #pragma unroll
        for (int j = 0; j < 4; j++)
            #pragma unroll
            for (int q = 0; q < 4; q++) { accK[i][j][q] = 0.f; accV[i][j][q] = 0.f; }

    auto loadAB = [&](int buf, int k0) {
        __half* Ab  = As  + buf * 128 * 72;
        __half* Bkb = Bks + buf * 64 * 136;
        __half* Bvb = Bvs + buf * 64 * 136;
        #pragma unroll
        for (int j = 0; j < 4; j++) {
            int id = tid + j * 256;
            int r = id >> 3, c = (id & 7) * 8;
            cpa16(Ab + r * 72 + c, Ag + (size_t)r * K + k0 + c);
        }
        #pragma unroll
        for (int j = 0; j < 4; j++) {
            int id = tid + j * 256;
            int r = id >> 4, c = (id & 15) * 8;
            cpa16(Bkb + r * 136 + c, Wkg + (size_t)(k0 + r) * N + c);
            cpa16(Bvb + r * 136 + c, Wvg + (size_t)(k0 + r) * N + c);
        }
        cp_commit();
    };

    const int nit = K / 64;
    loadAB(0, 0);
    for (int it = 0; it < nit; it++) {
        if (it + 1 < nit) loadAB((it + 1) & 1, (it + 1) * 64);
        if (it + 1 < nit) cp_wait<1>(); else cp_wait<0>();
        __syncthreads();
        const __half* Ab  = As  + (it & 1) * 128 * 72;
        const __half* Bkb = Bks + (it & 1) * 64 * 136;
        const __half* Bvb = Bvs + (it & 1) * 64 * 136;
        #pragma unroll
        for (int ks = 0; ks < 64; ks += 16) {
            uint32_t a[4][4], bk[4][2], bv[4][2];
            #pragma unroll
            for (int im = 0; im < 4; im++)
                ldA_x4(a[im], Ab, 72, wm + im * 16, ks, lane);
            ldB_pair(bk[0], bk[1], Bkb, 136, ks, wn,      lane);
            ldB_pair(bk[2], bk[3], Bkb, 136, ks, wn + 16, lane);
            ldB_pair(bv[0], bv[1], Bvb, 136, ks, wn,      lane);
            ldB_pair(bv[2], bv[3], Bvb, 136, ks, wn + 16, lane);
            #pragma unroll
            for (int im = 0; im < 4; im++)
                #pragma unroll
                for (int in_ = 0; in_ < 4; in_++) {
                    mma_f16(accK[im][in_], a[im], bk[in_]);
                    mma_f16(accV[im][in_], a[im], bv[in_]);
                }
        }
        __syncthreads();
    }

    #pragma unroll
    for (int im = 0; im < 4; im++) {
        #pragma unroll
        for (int in_ = 0; in_ < 4; in_++) {
            int r0 = by * 128 + wm + im * 16 + lr;
            int cb = bx * 128 + wn + in_ * 8 + 2 * lc;
            *(__half2*)(Ko + (size_t)r0 * N + cb) =
                __floats2half2_rn(accK[im][in_][0], accK[im][in_][1]);
            *(__half2*)(Ko + (size_t)(r0 + 8) * N + cb) =
                __floats2half2_rn(accK[im][in_][2], accK[im][in_][3]);
            *(__half2*)(Vo + (size_t)r0 * N + cb) =
                __floats2half2_rn(accV[im][in_][0], accV[im][in_][1]);
            *(__half2*)(Vo + (size_t)(r0 + 8) * N + cb) =
                __floats2half2_rn(accV[im][in_][2], accV[im][in_][3]);
        }
    }
}

// ============================================================
// Fused scores + softmax: 512 threads, 32 t-rows, s-chunk 256. (R8)
// ============================================================
__global__ void __launch_bounds__(512) scores_softmax(
    const __half* __restrict__ Q, const __half* __restrict__ Kg,
    const int* __restrict__ mask, __half* __restrict__ P)
{
    extern __shared__ __half sms[];
    __half* Es = sms;                 // [32][2056]
    __half* Ks = sms + 32 * 2056;     // 2 x [256][72]
    __half* Qs = Ks + 2 * 256 * 72;   // [32][72]

    int tid = threadIdx.x, lane = tid & 31, wid = tid >> 5;
    int lr = lane >> 2, lc = lane & 3;
    int bh = blockIdx.y, b = bh >> 4, h = bh & 15;
    int t0 = blockIdx.x * 32;
    int n0 = wid * 16;

    if (tid < 256) {
        int r = tid >> 3, c = (tid & 7) * 8;
        *(uint4*)&Qs[r * 72 + c] =
            *(const uint4*)(Q + (size_t)(b * Tt + t0 + r) * Hh + h * DK + c);
    }

    auto loadK = [&](int buf, int s0) {
        __half* Kb = Ks + buf * 256 * 72;
        #pragma unroll
        for (int j = 0; j < 4; j++) {
            int id = tid + j * 512;
            int r = id >> 3, c = (id & 7) * 8;
            cpa16(Kb + r * 72 + c, Kg + (size_t)(b * Ss + s0 + r) * Hh + h * DK + c);
        }
        cp_commit();
    };

    loadK(0, 0);
    __syncthreads();

    uint32_t qa[2][4][4];
    #pragma unroll
    for (int im = 0; im < 2; im++)
        #pragma unroll
        for (int kk = 0; kk < 4; kk++)
            ldA_x4(qa[im][kk], Qs, 72, im * 16, kk * 16, lane);

    for (int it = 0; it < 8; it++) {
        if (it + 1 < 8) loadK((it + 1) & 1, (it + 1) * 256);
        if (it + 1 < 8) cp_wait<1>(); else cp_wait<0>();
        __syncthreads();
        const __half* Kb = Ks + (it & 1) * 256 * 72;
        int s0 = it * 256;

        float acc[2][2][4];
        #pragma unroll
        for (int i = 0; i < 2; i++)
            #pragma unroll
            for (int j = 0; j < 2; j++)
                #pragma unroll
                for (int q = 0; q < 4; q++) acc[i][j][q] = 0.f;

        #pragma unroll
        for (int kk = 0; kk < 4; kk++) {
            uint32_t bf[2][2];
            ldBn_x4(bf[0], bf[1], Kb, 72, n0, kk * 16, lane);
            #pragma unroll
            for (int im = 0; im < 2; im++)
                #pragma unroll
                for (int in_ = 0; in_ < 2; in_++)
                    mma_f16(acc[im][in_], qa[im][kk], bf[in_]);
        }

        #pragma unroll
        for (int im = 0; im < 2; im++) {
            #pragma unroll
            for (int in_ = 0; in_ < 2; in_++) {
                int t = im * 16 + lr;
                int s = s0 + n0 + in_ * 8 + 2 * lc;
                *(__half2*)&Es[t * 2056 + s] =
                    __floats2half2_rn(acc[im][in_][0], acc[im][in_][1]);
                *(__half2*)&Es[(t + 8) * 2056 + s] =
                    __floats2half2_rn(acc[im][in_][2], acc[im][in_][3]);
            }
        }
        __syncthreads();
    }

    const int* mrow = mask + b * Ss;
    const __half minus3e4 = __float2half(-30000.f);
    #pragma unroll
    for (int rr = 0; rr < 2; rr++) {
        int r = wid * 2 + rr;
        uint4 E[8];
        float mx = -3.0e38f;
        #pragma unroll
        for (int i = 0; i < 8; i++) {
            int s = i * 256 + lane * 8;
            E[i] = *(uint4*)&Es[r * 2056 + s];
            int4 m0 = *(const int4*)&mrow[s];
            int4 m1 = *(const int4*)&mrow[s + 4];
            __half* hp = (__half*)&E[i];
            if (!m0.x) hp[0] = minus3e4;
            if (!m0.y) hp[1] = minus3e4;
            if (!m0.z) hp[2] = minus3e4;
            if (!m0.w) hp[3] = minus3e4;
            if (!m1.x) hp[4] = minus3e4;
            if (!m1.y) hp[5] = minus3e4;
            if (!m1.z) hp[6] = minus3e4;
            if (!m1.w) hp[7] = minus3e4;
            __half2* h2p = (__half2*)&E[i];
            #pragma unroll
            for (int j = 0; j < 4; j++) {
                float2 f = __half22float2(h2p[j]);
                mx = fmaxf(mx, fmaxf(f.x, f.y));
            }
        }
        #pragma unroll
        for (int o = 16; o; o >>= 1) mx = fmaxf(mx, __shfl_xor_sync(0xffffffffu, mx, o));

        float sum = 0.f;
        #pragma unroll
        for (int i = 0; i < 8; i++) {
            __half2* h2p = (__half2*)&E[i];
            #pragma unroll
            for (int j = 0; j < 4; j++) {
                float2 f = __half22float2(h2p[j]);
                float e0 = __expf(f.x - mx), e1 = __expf(f.y - mx);
                sum += e0 + e1;
                h2p[j] = __floats2half2_rn(e0, e1);
            }
        }
        #pragma unroll
        for (int o = 16; o; o >>= 1) sum += __shfl_xor_sync(0xffffffffu, sum, o);
        float inv = 1.0f / sum;

        __half* Pd = P + ((size_t)bh * Tt + t0 + r) * Ss;
        #pragma unroll
        for (int i = 0; i < 8; i++) {
            __half2* h2p = (__half2*)&E[i];
            #pragma unroll
            for (int j = 0; j < 4; j++) {
                float2 f = __half22float2(h2p[j]);
                h2p[j] = __floats2half2_rn(f.x * inv, f.y * inv);
            }
            int s = i * 256 + lane * 8;
            *(uint4*)(Pd + s) = E[i];
        }
    }
}

// ============================================================
// mean over heads
// ============================================================
__global__ void mean_kernel(const __half* __restrict__ P, float* __restrict__ out)
{
    const size_t TS = (size_t)Tt * Ss;
    size_t idx = (size_t)blockIdx.x * blockDim.x + threadIdx.x;
    size_t base = idx * 8;
    if (base >= (size_t)Bb * TS) return;
    size_t b = base / TS, r = base - b * TS;
    float s[8] = {0,0,0,0,0,0,0,0};
    #pragma unroll
    for (int h = 0; h < NH; h++) {
        uint4 v = *(const uint4*)(P + ((size_t)(b * NH + h)) * TS + r);
        const __half2* hp = (const __half2*)&v;
        #pragma unroll
        for (int j = 0; j < 4; j++) {
            float2 f = __half22float2(hp[j]);
            s[2*j] += f.x; s[2*j+1] += f.y;
        }
    }
    float4 o0 = make_float4(s[0]*0.0625f, s[1]*0.0625f, s[2]*0.0625f, s[3]*0.0625f);
    float4 o1 = make_float4(s[4]*0.0625f, s[5]*0.0625f, s[6]*0.0625f, s[7]*0.0625f);
    *(float4*)(out + base) = o0;
    *(float4*)(out + base + 4) = o1;
}

// ============================================================
// AV v2: block 256(t) x 64(d), 8 warps 4m x 2n, warp 64x32.
// mma:LDSM 2.67 (was 1.33). Dynamic smem 92 KB -> 2 CTAs/SM.
// ============================================================
__global__ void __launch_bounds__(256) av_f16(
    const __half* __restrict__ P, const __half* __restrict__ V,
    __half* __restrict__ Cc)
{
    extern __shared__ __half smv[];
    __half* Ps = smv;                  // 2 x [256][72]
    __half* Vs = smv + 2 * 256 * 72;   // 2 x [64][72]
    int tid = threadIdx.x, lane = tid & 31, wid = tid >> 5;
    int lr = lane >> 2, lc = lane & 3;
    int wm = (wid >> 1) * 64, wn = (wid & 1) * 32;
    int bh = blockIdx.y, b = bh >> 4, h = bh & 15;
    int t0 = blockIdx.x * 256;

    float acc[4][4][4];
    #pragma unroll
    for (int i = 0; i < 4; i++)
        #pragma unroll
        for (int j = 0; j < 4; j++)
            #pragma unroll
            for (int q = 0; q < 4; q++) acc[i][j][q] = 0.f;

    const __half* Pbase = P + ((size_t)bh * Tt + t0) * Ss;
    const __half* Vbase = V + (size_t)b * Ss * Hh + h * DK;

    auto loadPV = [&](int buf, int s0) {
        __half* Pb = Ps + buf * 256 * 72;
        __half* Vb = Vs + buf * 64 * 72;
        #pragma unroll
        for (int j = 0; j < 8; j++) {
            int id = tid + j * 256;
            int r = id >> 3, c = (id & 7) * 8;
            cpa16(Pb + r * 72 + c, Pbase + (size_t)r * Ss + s0 + c);
        }
        #pragma unroll
        for (int j = 0; j < 2; j++) {
            int id = tid + j * 256;
            int r = id >> 3, c = (id & 7) * 8;
            cpa16(Vb + r * 72 + c, Vbase + (size_t)(s0 + r) * Hh + c);
        }
        cp_commit();
    };

    loadPV(0, 0);
    for (int it = 0; it < Ss / 64; it++) {
        if (it + 1 < Ss / 64) loadPV((it + 1) & 1, (it + 1) * 64);
        if (it + 1 < Ss / 64) cp_wait<1>(); else cp_wait<0>();
        __syncthreads();
        const __half* Pb = Ps + (it & 1) * 256 * 72;
        const __half* Vb = Vs + (it & 1) * 64 * 72;

        #pragma unroll
        for (int kk = 0; kk < 4; kk++) {
            uint32_t a[4][4], b2[4][2];
            #pragma unroll
            for (int im = 0; im < 4; im++)
                ldA_x4(a[im], Pb, 72, wm + im * 16, kk * 16, lane);
            ldB_pair(b2[0], b2[1], Vb, 72, kk * 16, wn,      lane);
            ldB_pair(b2[2], b2[3], Vb, 72, kk * 16, wn + 16, lane);
            #pragma unroll
            for (int im = 0; im < 4; im++)
                #pragma unroll
                for (int in_ = 0; in_ < 4; in_++)
                    mma_f16(acc[im][in_], a[im], b2[in_]);
        }
        __syncthreads();
    }

    #pragma unroll
    for (int im = 0; im < 4; im++) {
        #pragma unroll
        for (int in_ = 0; in_ < 4; in_++) {
            int r0 = t0 + wm + im * 16 + lr;
            int cb = wn + (in_ & 1) * 8 + (in_ >> 1) * 16 + 2 * lc;
            // ldB_pair(b2[0],b2[1]) covers n= wn..wn+15; b2[2],b2[3] -> wn+16..wn+31
            *(__half2*)(Cc + (size_t)(b * Tt + r0) * Hh + h * DK + cb) =
                __floats2half2_rn(acc[im][in_][0], acc[im][in_][1]);
            *(__half2*)(Cc + (size_t)(b * Tt + r0 + 8) * Hh + h * DK + cb) =
                __floats2half2_rn(acc[im][in_][2], acc[im][in_][3]);
        }
    }
}

// ============================================================
extern "C" void kernel_launch(void* const* d_in, const int* in_sizes, int n_in,
                              void* d_out, int out_size)
{
    const float* hiddens = (const float*)d_in[0];
    const float* qh      = (const float*)d_in[1];
    const int*   mask    = (const int*)  d_in[2];
    const float* W_q     = (const float*)d_in[3];
    const float* b_q     = (const float*)d_in[4];
    const float* W_k     = (const float*)d_in[5];
    const float* W_v     = (const float*)d_in[6];
    const float* W_o     = (const float*)d_in[7];
    const float* b_o     = (const float*)d_in[8];
    float* out = (float*)d_out;

    __half *pH, *pQH, *pWq, *pWk, *pWv, *pWo, *pQ, *pK, *pV, *pP, *pC;
    cudaGetSymbolAddress((void**)&pH,  g_H);
    cudaGetSymbolAddress((void**)&pQH, g_QH);
    cudaGetSymbolAddress((void**)&pWq, g_Wq);
    cudaGetSymbolAddress((void**)&pWk, g_Wk);
    cudaGetSymbolAddress((void**)&pWv, g_Wv);
    cudaGetSymbolAddress((void**)&pWo, g_Wo);
    cudaGetSymbolAddress((void**)&pQ,  g_Q);
    cudaGetSymbolAddress((void**)&pK,  g_K);
    cudaGetSymbolAddress((void**)&pV,  g_V);
    cudaGetSymbolAddress((void**)&pP,  g_P);
    cudaGetSymbolAddress((void**)&pC,  g_C);

    const int GEMM_SMEM = (2*128*72 + 2*64*136) * 2;
    const int KV_SMEM   = (2*128*72 + 4*64*136) * 2;
    const int SS_SMEM   = (32*2056 + 2*256*72 + 32*72) * 2;
    const int AV_SMEM   = (2*256*72 + 2*64*72) * 2;
    cudaFuncSetAttribute(gemm16<true , true >, cudaFuncAttributeMaxDynamicSharedMemorySize, GEMM_SMEM);
    cudaFuncSetAttribute(gemm16<false, true >, cudaFuncAttributeMaxDynamicSharedMemorySize, GEMM_SMEM);
    cudaFuncSetAttribute(kvgemm16, cudaFuncAttributeMaxDynamicSharedMemorySize, KV_SMEM);
    cudaFuncSetAttribute(scores_softmax, cudaFuncAttributeMaxDynamicSharedMemorySize, SS_SMEM);
    cudaFuncSetAttribute(av_f16, cudaFuncAttributeMaxDynamicSharedMemorySize, AV_SMEM);

    // fp32 -> fp16 converts
    f2h4<<<(Bb*Ss*Hh/4 + 255)/256, 256>>>(hiddens, pH,  Bb*Ss*Hh/4);
    f2h4<<<(Bb*Tt*Hh/4 + 255)/256, 256>>>(qh,      pQH, Bb*Tt*Hh/4);
    f2h4<<<(Hh*Hh/4 + 255)/256, 256>>>(W_q, pWq, Hh*Hh/4);
    f2h4<<<(Hh*Hh/4 + 255)/256, 256>>>(W_k, pWk, Hh*Hh/4);
    f2h4<<<(Hh*Hh/4 + 255)/256, 256>>>(W_v, pWv, Hh*Hh/4);
    f2h4<<<(Hh*Hh/4 + 255)/256, 256>>>(W_o, pWo, Hh*Hh/4);

    // Projections: Q (scaled), fused K+V
    gemm16<true , true ><<<dim3(8, 32), 256, GEMM_SMEM>>>(pQH, pWq, b_q, pQ, Bb*Tt, Hh, Hh, 0.125f);
    kvgemm16<<<dim3(8, 128), 256, KV_SMEM>>>(pH, pWk, pWv, pK, pV);

    // Fused scores + softmax
    scores_softmax<<<dim3(Tt/32, Bb*NH), 512, SS_SMEM>>>(pQ, pK, mask, pP);

    // Head-mean
    {
        size_t n8 = (size_t)Bb * Tt * Ss / 8;
        mean_kernel<<<(unsigned)((n8 + 255) / 256), 256>>>(pP, out + (size_t)Bb*Tt*Hh);
    }

    // AV and output projection
    av_f16<<<dim3(Tt/256, Bb*NH), 256, AV_SMEM>>>(pP, pV, pC);
    gemm16<false, true ><<<dim3(8, 32), 256, GEMM_SMEM>>>(pC, pWo, b_o, out, Bb*Tt, Hh, Hh, 1.0f);
}

// round 13
// speedup vs baseline: 1.1626x; 1.0127x over previous
#include <cuda_runtime.h>
#include <cuda_fp16.h>
#include <math.h>
#include <stdint.h>

#define Bb 8
#define Ss 2048
#define Tt 512
#define Hh 1024
#define NH 16
#define DK 64

// ---- scratch ----
__device__ __half g_H [(size_t)Bb*Ss*Hh];
__device__ __half g_QH[(size_t)Bb*Tt*Hh];
__device__ __half g_Wq[Hh*Hh], g_Wk[Hh*Hh], g_Wv[Hh*Hh], g_Wo[Hh*Hh];
__device__ __half g_Q [(size_t)Bb*Tt*Hh];
__device__ __half g_K [(size_t)Bb*Ss*Hh];
__device__ __half g_V [(size_t)Bb*Ss*Hh];
__device__ __half g_P [(size_t)Bb*NH*Tt*Ss];
__device__ __half g_C [(size_t)Bb*Tt*Hh];

// ------------------------------------------------------------
__device__ __forceinline__ uint32_t h2u(__half2 v) { return *(uint32_t*)&v; }

__device__ __forceinline__ void mma_f16(float* c, const uint32_t* a, const uint32_t* b) {
    asm volatile(
        "mma.sync.aligned.m16n8k16.row.col.f32.f16.f16.f32 "
        "{%0,%1,%2,%3}, {%4,%5,%6,%7}, {%8,%9}, {%0,%1,%2,%3};"
        : "+f"(c[0]), "+f"(c[1]), "+f"(c[2]), "+f"(c[3])
        : "r"(a[0]), "r"(a[1]), "r"(a[2]), "r"(a[3]),
          "r"(b[0]), "r"(b[1]));
}

__device__ __forceinline__ void cpa16(void* dst, const void* src) {
    uint32_t d = (uint32_t)__cvta_generic_to_shared(dst);
    asm volatile("cp.async.cg.shared.global [%0], [%1], 16;" :: "r"(d), "l"(src));
}
__device__ __forceinline__ void cp_commit() { asm volatile("cp.async.commit_group;"); }
template<int N_> __device__ __forceinline__ void cp_wait() {
    asm volatile("cp.async.wait_group %0;" :: "n"(N_));
}

__device__ __forceinline__ void ldsm_x4(uint32_t* r, uint32_t addr) {
    asm volatile("ldmatrix.sync.aligned.m8n8.x4.shared.b16 {%0,%1,%2,%3}, [%4];"
        : "=r"(r[0]), "=r"(r[1]), "=r"(r[2]), "=r"(r[3]) : "r"(addr));
}
__device__ __forceinline__ void ldsm_x4_t(uint32_t* r, uint32_t addr) {
    asm volatile("ldmatrix.sync.aligned.m8n8.x4.trans.shared.b16 {%0,%1,%2,%3}, [%4];"
        : "=r"(r[0]), "=r"(r[1]), "=r"(r[2]), "=r"(r[3]) : "r"(addr));
}

__device__ __forceinline__ void ldA_x4(uint32_t* r, const __half* S, int LD,
                                       int row0, int col0, int lane) {
    int g = lane >> 3, rr = lane & 7;
    const __half* p = S + (size_t)(row0 + (g & 1) * 8 + rr) * LD + col0 + (g >> 1) * 8;
    ldsm_x4(r, (uint32_t)__cvta_generic_to_shared(p));
}
__device__ __forceinline__ void ldBn_x4(uint32_t* b0, uint32_t* b1,
                                        const __half* S, int LD, int n0, int k0, int lane) {
    int g = lane >> 3, rr = lane & 7;
    const __half* p = S + (n0 + (g & 1) * 8 + rr) * LD + k0 + (g >> 1) * 8;
    uint32_t q[4];
    ldsm_x4(q, (uint32_t)__cvta_generic_to_shared(p));
    b0[0] = q[0]; b0[1] = q[2];
    b1[0] = q[1]; b1[1] = q[3];
}
__device__ __forceinline__ void ldB_pair(uint32_t* b0, uint32_t* b1,
                                         const __half* S, int RS, int k0, int n0, int lane) {
    int g = lane >> 3, r = lane & 7;
    int row = k0 + r + (g & 1) * 8;
    int col = n0 + (g >> 1) * 8;
    uint32_t q[4];
    ldsm_x4_t(q, (uint32_t)__cvta_generic_to_shared(S + row * RS + col));
    b0[0] = q[0]; b0[1] = q[1];
    b1[0] = q[2]; b1[1] = q[3];
}

// ============================================================
__global__ void f2h4(const float* __restrict__ in, __half* __restrict__ out, int n4) {
    int i = blockIdx.x * blockDim.x + threadIdx.x;
    if (i < n4) {
        float4 v = ((const float4*)in)[i];
        uint2 u;
        u.x = h2u(__floats2half2_rn(v.x, v.y));
        u.y = h2u(__floats2half2_rn(v.z, v.w));
        ((uint2*)out)[i] = u;
    }
}

// Batched 4-weight convert: blockIdx.y selects which weight.
__global__ void f2h4w(const float* w0, const float* w1,
                      const float* w2, const float* w3,
                      __half* o0, __half* o1, __half* o2, __half* o3)
{
    const int n4 = Hh * Hh / 4;
    int i = blockIdx.x * blockDim.x + threadIdx.x;
    if (i >= n4) return;
    const float* in; __half* out;
    switch (blockIdx.y) {
        case 0: in = w0; out = o0; break;
        case 1: in = w1; out = o1; break;
        case 2: in = w2; out = o2; break;
        default: in = w3; out = o3; break;
    }
    float4 v = ((const float4*)in)[i];
    uint2 u;
    u.x = h2u(__floats2half2_rn(v.x, v.y));
    u.y = h2u(__floats2half2_rn(v.z, v.w));
    ((uint2*)out)[i] = u;
}

// ============================================================
// fp16 GEMM: 128x128 tile, BK=64, cp.async dbl-buf, 8 warps 64x32.
// ============================================================
template<bool F16OUT, bool HAS_BIAS>
__global__ void __launch_bounds__(256) gemm16(
    const __half* __restrict__ A, const __half* __restrict__ W,
    const float* __restrict__ bias, void* __restrict__ Cout,
    int M, int N, int K, float scale)
{
    extern __shared__ __half smx[];
    __half* As = smx;                  // 2 x [128][72]
    __half* Bs = smx + 2 * 128 * 72;   // 2 x [64][136]
    int tid = threadIdx.x, lane = tid & 31, wid = tid >> 5;
    int lr = lane >> 2, lc = lane & 3;
    int wm = (wid >> 2) * 64, wn = (wid & 3) * 32;
    int bx = blockIdx.x, by = blockIdx.y;

    const __half* Ag = A + (size_t)by * 128 * K;
    const __half* Wg = W + bx * 128;

    float acc[4][4][4];
    #pragma unroll
    for (int i = 0; i < 4; i++)
        #pragma unroll
        for (int j = 0; j < 4; j++)
            #pragma unroll
            for (int q = 0; q < 4; q++) acc[i][j][q] = 0.f;

    auto loadAB = [&](int buf, int k0) {
        __half* Ab = As + buf * 128 * 72;
        __half* Bb2 = Bs + buf * 64 * 136;
        #pragma unroll
        for (int j = 0; j < 4; j++) {
            int id = tid + j * 256;
            int r = id >> 3, c = (id & 7) * 8;
            cpa16(Ab + r * 72 + c, Ag + (size_t)r * K + k0 + c);
        }
        #pragma unroll
        for (int j = 0; j < 4; j++) {
            int id = tid + j * 256;
            int r = id >> 4, c = (id & 15) * 8;
            cpa16(Bb2 + r * 136 + c, Wg + (size_t)(k0 + r) * N + c);
        }
        cp_commit();
    };

    int nit = K / 64;
    loadAB(0, 0);
    for (int it = 0; it < nit; it++) {
        if (it + 1 < nit) loadAB((it + 1) & 1, (it + 1) * 64);
        if (it + 1 < nit) cp_wait<1>(); else cp_wait<0>();
        __syncthreads();
        const __half* Ab = As + (it & 1) * 128 * 72;
        const __half* Bb2 = Bs + (it & 1) * 64 * 136;
        #pragma unroll
        for (int ks = 0; ks < 64; ks += 16) {
            uint32_t a[4][4], b[4][2];
            #pragma unroll
            for (int im = 0; im < 4; im++)
                ldA_x4(a[im], Ab, 72, wm + im * 16, ks, lane);
            ldB_pair(b[0], b[1], Bb2, 136, ks, wn,      lane);
            ldB_pair(b[2], b[3], Bb2, 136, ks, wn + 16, lane);
            #pragma unroll
            for (int im = 0; im < 4; im++)
                #pragma unroll
                for (int in_ = 0; in_ < 4; in_++)
                    mma_f16(acc[im][in_], a[im], b[in_]);
        }
        __syncthreads();
    }

    #pragma unroll
    for (int im = 0; im < 4; im++) {
        #pragma unroll
        for (int in_ = 0; in_ < 4; in_++) {
            int r0 = by * 128 + wm + im * 16 + lr;
            int cb = bx * 128 + wn + in_ * 8 + 2 * lc;
            float b0 = HAS_BIAS ? bias[cb] : 0.f;
            float b1 = HAS_BIAS ? bias[cb + 1] : 0.f;
            float x0 = (acc[im][in_][0] + b0) * scale;
            float x1 = (acc[im][in_][1] + b1) * scale;
            float x2 = (acc[im][in_][2] + b0) * scale;
            float x3 = (acc[im][in_][3] + b1) * scale;
            if (F16OUT) {
                __half* C = (__half*)Cout;
                *(__half2*)(C + (size_t)r0 * N + cb)       = __floats2half2_rn(x0, x1);
                *(__half2*)(C + (size_t)(r0 + 8) * N + cb) = __floats2half2_rn(x2, x3);
            } else {
                float* C = (float*)Cout;
                *(float2*)(C + (size_t)r0 * N + cb)       = make_float2(x0, x1);
                *(float2*)(C + (size_t)(r0 + 8) * N + cb) = make_float2(x2, x3);
            }
        }
    }
}

// ============================================================
// Fused K+V projection (legacy HMMA)
// ============================================================
__global__ void __launch_bounds__(256, 1) kvgemm16(
    const __half* __restrict__ A, const __half* __restrict__ Wk,
    const __half* __restrict__ Wv, __half* __restrict__ Ko,
    __half* __restrict__ Vo)
{
    const int N = Hh, K = Hh;
    extern __shared__ __half smk[];
    __half* As  = smk;                    // 2 x [128][72]
    __half* Bks = smk + 2 * 128 * 72;     // 2 x [64][136]
    __half* Bvs = Bks + 2 * 64 * 136;     // 2 x [64][136]
    int tid = threadIdx.x, lane = tid & 31, wid = tid >> 5;
    int lr = lane >> 2, lc = lane & 3;
    int wm = (wid >> 2) * 64, wn = (wid & 3) * 32;
    int bx = blockIdx.x, by = blockIdx.y;

    const __half* Ag  = A  + (size_t)by * 128 * K;
    const __half* Wkg = Wk + bx * 128;
    const __half* Wvg = Wv + bx * 128;

    float accK[4][4][4], accV[4][4][4];
    #pragma unroll
    for (int i = 0; i < 4; i++)
        #pragma unroll
        for (int j = 0; j < 4; j++)
            #pragma unroll
            for (int q = 0; q < 4; q++) { accK[i][j][q] = 0.f; accV[i][j][q] = 0.f; }

    auto loadAB = [&](int buf, int k0) {
        __half* Ab  = As  + buf * 128 * 72;
        __half* Bkb = Bks + buf * 64 * 136;
        __half* Bvb = Bvs + buf * 64 * 136;
        #pragma unroll
        for (int j = 0; j < 4; j++) {
            int id = tid + j * 256;
            int r = id >> 3, c = (id & 7) * 8;
            cpa16(Ab + r * 72 + c, Ag + (size_t)r * K + k0 + c);
        }
        #pragma unroll
        for (int j = 0; j < 4; j++) {
            int id = tid + j * 256;
            int r = id >> 4, c = (id & 15) * 8;
            cpa16(Bkb + r * 136 + c, Wkg + (size_t)(k0 + r) * N + c);
            cpa16(Bvb + r * 136 + c, Wvg + (size_t)(k0 + r) * N + c);
        }
        cp_commit();
    };

    const int nit = K / 64;
    loadAB(0, 0);
    for (int it = 0; it < nit; it++) {
        if (it + 1 < nit) loadAB((it + 1) & 1, (it + 1) * 64);
        if (it + 1 < nit) cp_wait<1>(); else cp_wait<0>();
        __syncthreads();
        const __half* Ab  = As  + (it & 1) * 128 * 72;
        const __half* Bkb = Bks + (it & 1) * 64 * 136;
        const __half* Bvb = Bvs + (it & 1) * 64 * 136;
        #pragma unroll
        for (int ks = 0; ks < 64; ks += 16) {
            uint32_t a[4][4], bk[4][2], bv[4][2];
            #pragma unroll
            for (int im = 0; im < 4; im++)
                ldA_x4(a[im], Ab, 72, wm + im * 16, ks, lane);
            ldB_pair(bk[0], bk[1], Bkb, 136, ks, wn,      lane);
            ldB_pair(bk[2], bk[3], Bkb, 136, ks, wn + 16, lane);
            ldB_pair(bv[0], bv[1], Bvb, 136, ks, wn,      lane);
            ldB_pair(bv[2], bv[3], Bvb, 136, ks, wn + 16, lane);
            #pragma unroll
            for (int im = 0; im < 4; im++)
                #pragma unroll
                for (int in_ = 0; in_ < 4; in_++) {
                    mma_f16(accK[im][in_], a[im], bk[in_]);
                    mma_f16(accV[im][in_], a[im], bv[in_]);
                }
        }
        __syncthreads();
    }

    #pragma unroll
    for (int im = 0; im < 4; im++) {
        #pragma unroll
        for (int in_ = 0; in_ < 4; in_++) {
            int r0 = by * 128 + wm + im * 16 + lr;
            int cb = bx * 128 + wn + in_ * 8 + 2 * lc;
            *(__half2*)(Ko + (size_t)r0 * N + cb) =
                __floats2half2_rn(accK[im][in_][0], accK[im][in_][1]);
            *(__half2*)(Ko + (size_t)(r0 + 8) * N + cb) =
                __floats2half2_rn(accK[im][in_][2], accK[im][in_][3]);
            *(__half2*)(Vo + (size_t)r0 * N + cb) =
                __floats2half2_rn(accV[im][in_][0], accV[im][in_][1]);
            *(__half2*)(Vo + (size_t)(r0 + 8) * N + cb) =
                __floats2half2_rn(accV[im][in_][2], accV[im][in_][3]);
        }
    }
}

// ============================================================
// Fused scores + softmax: 512 threads, 32 t-rows, s-chunk 256.
// ============================================================
__global__ void __launch_bounds__(512) scores_softmax(
    const __half* __restrict__ Q, const __half* __restrict__ Kg,
    const int* __restrict__ mask, __half* __restrict__ P)
{
    extern __shared__ __half sms[];
    __half* Es = sms;                 // [32][2056]
    __half* Ks = sms + 32 * 2056;     // 2 x [256][72]
    __half* Qs = Ks + 2 * 256 * 72;   // [32][72]

    int tid = threadIdx.x, lane = tid & 31, wid = tid >> 5;
    int lr = lane >> 2, lc = lane & 3;
    int bh = blockIdx.y, b = bh >> 4, h = bh & 15;
    int t0 = blockIdx.x * 32;
    int n0 = wid * 16;

    if (tid < 256) {
        int r = tid >> 3, c = (tid & 7) * 8;
        *(uint4*)&Qs[r * 72 + c] =
            *(const uint4*)(Q + (size_t)(b * Tt + t0 + r) * Hh + h * DK + c);
    }

    auto loadK = [&](int buf, int s0) {
        __half* Kb = Ks + buf * 256 * 72;
        #pragma unroll
        for (int j = 0; j < 4; j++) {
            int id = tid + j * 512;
            int r = id >> 3, c = (id & 7) * 8;
            cpa16(Kb + r * 72 + c, Kg + (size_t)(b * Ss + s0 + r) * Hh + h * DK + c);
        }
        cp_commit();
    };

    loadK(0, 0);
    __syncthreads();

    uint32_t qa[2][4][4];
    #pragma unroll
    for (int im = 0; im < 2; im++)
        #pragma unroll
        for (int kk = 0; kk < 4; kk++)
            ldA_x4(qa[im][kk], Qs, 72, im * 16, kk * 16, lane);

    for (int it = 0; it < 8; it++) {
        if (it + 1 < 8) loadK((it + 1) & 1, (it + 1) * 256);
        if (it + 1 < 8) cp_wait<1>(); else cp_wait<0>();
        __syncthreads();
        const __half* Kb = Ks + (it & 1) * 256 * 72;
        int s0 = it * 256;

        float acc[2][2][4];
        #pragma unroll
        for (int i = 0; i < 2; i++)
            #pragma unroll
            for (int j = 0; j < 2; j++)
                #pragma unroll
                for (int q = 0; q < 4; q++) acc[i][j][q] = 0.f;

        #pragma unroll
        for (int kk = 0; kk < 4; kk++) {
            uint32_t bf[2][2];
            ldBn_x4(bf[0], bf[1], Kb, 72, n0, kk * 16, lane);
            #pragma unroll
            for (int im = 0; im < 2; im++)
                #pragma unroll
                for (int in_ = 0; in_ < 2; in_++)
                    mma_f16(acc[im][in_], qa[im][kk], bf[in_]);
        }

        #pragma unroll
        for (int im = 0; im < 2; im++) {
            #pragma unroll
            for (int in_ = 0; in_ < 2; in_++) {
                int t = im * 16 + lr;
                int s = s0 + n0 + in_ * 8 + 2 * lc;
                *(__half2*)&Es[t * 2056 + s] =
                    __floats2half2_rn(acc[im][in_][0], acc[im][in_][1]);
                *(__half2*)&Es[(t + 8) * 2056 + s] =
                    __floats2half2_rn(acc[im][in_][2], acc[im][in_][3]);
            }
        }
        __syncthreads();
    }

    const int* mrow = mask + b * Ss;
    const __half minus3e4 = __float2half(-30000.f);
    #pragma unroll
    for (int rr = 0; rr < 2; rr++) {
        int r = wid * 2 + rr;
        uint4 E[8];
        float mx = -3.0e38f;
        #pragma unroll
        for (int i = 0; i < 8; i++) {
            int s = i * 256 + lane * 8;
            E[i] = *(uint4*)&Es[r * 2056 + s];
            int4 m0 = *(const int4*)&mrow[s];
            int4 m1 = *(const int4*)&mrow[s + 4];
            __half* hp = (__half*)&E[i];
            if (!m0.x) hp[0] = minus3e4;
            if (!m0.y) hp[1] = minus3e4;
            if (!m0.z) hp[2] = minus3e4;
            if (!m0.w) hp[3] = minus3e4;
            if (!m1.x) hp[4] = minus3e4;
            if (!m1.y) hp[5] = minus3e4;
            if (!m1.z) hp[6] = minus3e4;
            if (!m1.w) hp[7] = minus3e4;
            __half2* h2p = (__half2*)&E[i];
            #pragma unroll
            for (int j = 0; j < 4; j++) {
                float2 f = __half22float2(h2p[j]);
                mx = fmaxf(mx, fmaxf(f.x, f.y));
            }
        }
        #pragma unroll
        for (int o = 16; o; o >>= 1) mx = fmaxf(mx, __shfl_xor_sync(0xffffffffu, mx, o));

        float sum = 0.f;
        #pragma unroll
        for (int i = 0; i < 8; i++) {
            __half2* h2p = (__half2*)&E[i];
            #pragma unroll
            for (int j = 0; j < 4; j++) {
                float2 f = __half22float2(h2p[j]);
                float e0 = __expf(f.x - mx), e1 = __expf(f.y - mx);
                sum += e0 + e1;
                h2p[j] = __floats2half2_rn(e0, e1);
            }
        }
        #pragma unroll
        for (int o = 16; o; o >>= 1) sum += __shfl_xor_sync(0xffffffffu, sum, o);
        float inv = 1.0f / sum;

        __half* Pd = P + ((size_t)bh * Tt + t0 + r) * Ss;
        #pragma unroll
        for (int i = 0; i < 8; i++) {
            __half2* h2p = (__half2*)&E[i];
            #pragma unroll
            for (int j = 0; j < 4; j++) {
                float2 f = __half22float2(h2p[j]);
                h2p[j] = __floats2half2_rn(f.x * inv, f.y * inv);
            }
            int s = i * 256 + lane * 8;
            *(uint4*)(Pd + s) = E[i];
        }
    }
}

// ============================================================
// mean over heads
// ============================================================
__global__ void mean_kernel(const __half* __restrict__ P, float* __restrict__ out)
{
    const size_t TS = (size_t)Tt * Ss;
    size_t idx = (size_t)blockIdx.x * blockDim.x + threadIdx.x;
    size_t base = idx * 8;
    if (base >= (size_t)Bb * TS) return;
    size_t b = base / TS, r = base - b * TS;
    float s[8] = {0,0,0,0,0,0,0,0};
    #pragma unroll
    for (int h = 0; h < NH; h++) {
        uint4 v = *(const uint4*)(P + ((size_t)(b * NH + h)) * TS + r);
        const __half2* hp = (const __half2*)&v;
        #pragma unroll
        for (int j = 0; j < 4; j++) {
            float2 f = __half22float2(hp[j]);
            s[2*j] += f.x; s[2*j+1] += f.y;
        }
    }
    float4 o0 = make_float4(s[0]*0.0625f, s[1]*0.0625f, s[2]*0.0625f, s[3]*0.0625f);
    float4 o1 = make_float4(s[4]*0.0625f, s[5]*0.0625f, s[6]*0.0625f, s[7]*0.0625f);
    *(float4*)(out + base) = o0;
    *(float4*)(out + base + 4) = o1;
}

// ============================================================
// AV v2: block 256(t) x 64(d), 8 warps 4m x 2n, warp 64x32.
// ============================================================
__global__ void __launch_bounds__(256) av_f16(
    const __half* __restrict__ P, const __half* __restrict__ V,
    __half* __restrict__ Cc)
{
    extern __shared__ __half smv[];
    __half* Ps = smv;                  // 2 x [256][72]
    __half* Vs = smv + 2 * 256 * 72;   // 2 x [64][72]
    int tid = threadIdx.x, lane = tid & 31, wid = tid >> 5;
    int lr = lane >> 2, lc = lane & 3;
    int wm = (wid >> 1) * 64, wn = (wid & 1) * 32;
    int bh = blockIdx.y, b = bh >> 4, h = bh & 15;
    int t0 = blockIdx.x * 256;

    float acc[4][4][4];
    #pragma unroll
    for (int i = 0; i < 4; i++)
        #pragma unroll
        for (int j = 0; j < 4; j++)
            #pragma unroll
            for (int q = 0; q < 4; q++) acc[i][j][q] = 0.f;

    const __half* Pbase = P + ((size_t)bh * Tt + t0) * Ss;
    const __half* Vbase = V + (size_t)b * Ss * Hh + h * DK;

    auto loadPV = [&](int buf, int s0) {
        __half* Pb = Ps + buf * 256 * 72;
        __half* Vb = Vs + buf * 64 * 72;
        #pragma unroll
        for (int j = 0; j < 8; j++) {
            int id = tid + j * 256;
            int r = id >> 3, c = (id & 7) * 8;
            cpa16(Pb + r * 72 + c, Pbase + (size_t)r * Ss + s0 + c);
        }
        #pragma unroll
        for (int j = 0; j < 2; j++) {
            int id = tid + j * 256;
            int r = id >> 3, c = (id & 7) * 8;
            cpa16(Vb + r * 72 + c, Vbase + (size_t)(s0 + r) * Hh + c);
        }
        cp_commit();
    };

    loadPV(0, 0);
    for (int it = 0; it < Ss / 64; it++) {
        if (it + 1 < Ss / 64) loadPV((it + 1) & 1, (it + 1) * 64);
        if (it + 1 < Ss / 64) cp_wait<1>(); else cp_wait<0>();
        __syncthreads();
        const __half* Pb = Ps + (it & 1) * 256 * 72;
        const __half* Vb = Vs + (it & 1) * 64 * 72;

        #pragma unroll
        for (int kk = 0; kk < 4; kk++) {
            uint32_t a[4][4], b2[4][2];
            #pragma unroll
            for (int im = 0; im < 4; im++)
                ldA_x4(a[im], Pb, 72, wm + im * 16, kk * 16, lane);
            ldB_pair(b2[0], b2[1], Vb, 72, kk * 16, wn,      lane);
            ldB_pair(b2[2], b2[3], Vb, 72, kk * 16, wn + 16, lane);
            #pragma unroll
            for (int im = 0; im < 4; im++)
                #pragma unroll
                for (int in_ = 0; in_ < 4; in_++)
                    mma_f16(acc[im][in_], a[im], b2[in_]);
        }
        __syncthreads();
    }

    #pragma unroll
    for (int im = 0; im < 4; im++) {
        #pragma unroll
        for (int in_ = 0; in_ < 4; in_++) {
            int r0 = t0 + wm + im * 16 + lr;
            int cb = wn + (in_ & 1) * 8 + (in_ >> 1) * 16 + 2 * lc;
            *(__half2*)(Cc + (size_t)(b * Tt + r0) * Hh + h * DK + cb) =
                __floats2half2_rn(acc[im][in_][0], acc[im][in_][1]);
            *(__half2*)(Cc + (size_t)(b * Tt + r0 + 8) * Hh + h * DK + cb) =
                __floats2half2_rn(acc[im][in_][2], acc[im][in_][3]);
        }
    }
}

// ============================================================
extern "C" void kernel_launch(void* const* d_in, const int* in_sizes, int n_in,
                              void* d_out, int out_size)
{
    const float* hiddens = (const float*)d_in[0];
    const float* qh      = (const float*)d_in[1];
    const int*   mask    = (const int*)  d_in[2];
    const float* W_q     = (const float*)d_in[3];
    const float* b_q     = (const float*)d_in[4];
    const float* W_k     = (const float*)d_in[5];
    const float* W_v     = (const float*)d_in[6];
    const float* W_o     = (const float*)d_in[7];
    const float* b_o     = (const float*)d_in[8];
    float* out = (float*)d_out;

    __half *pH, *pQH, *pWq, *pWk, *pWv, *pWo, *pQ, *pK, *pV, *pP, *pC;
    cudaGetSymbolAddress((void**)&pH,  g_H);
    cudaGetSymbolAddress((void**)&pQH, g_QH);
    cudaGetSymbolAddress((void**)&pWq, g_Wq);
    cudaGetSymbolAddress((void**)&pWk, g_Wk);
    cudaGetSymbolAddress((void**)&pWv, g_Wv);
    cudaGetSymbolAddress((void**)&pWo, g_Wo);
    cudaGetSymbolAddress((void**)&pQ,  g_Q);
    cudaGetSymbolAddress((void**)&pK,  g_K);
    cudaGetSymbolAddress((void**)&pV,  g_V);
    cudaGetSymbolAddress((void**)&pP,  g_P);
    cudaGetSymbolAddress((void**)&pC,  g_C);

    const int GEMM_SMEM = (2*128*72 + 2*64*136) * 2;
    const int KV_SMEM   = (2*128*72 + 4*64*136) * 2;
    const int SS_SMEM   = (32*2056 + 2*256*72 + 32*72) * 2;
    const int AV_SMEM   = (2*256*72 + 2*64*72) * 2;
    cudaFuncSetAttribute(gemm16<true , true >, cudaFuncAttributeMaxDynamicSharedMemorySize, GEMM_SMEM);
    cudaFuncSetAttribute(gemm16<false, true >, cudaFuncAttributeMaxDynamicSharedMemorySize, GEMM_SMEM);
    cudaFuncSetAttribute(kvgemm16, cudaFuncAttributeMaxDynamicSharedMemorySize, KV_SMEM);
    cudaFuncSetAttribute(scores_softmax, cudaFuncAttributeMaxDynamicSharedMemorySize, SS_SMEM);
    cudaFuncSetAttribute(av_f16, cudaFuncAttributeMaxDynamicSharedMemorySize, AV_SMEM);

    // Side stream + events for graph-capturable forking.
    cudaStream_t s2;
    cudaEvent_t eFork1, eJoin1, eFork2, eJoin2;
    cudaStreamCreateWithFlags(&s2, cudaStreamNonBlocking);
    cudaEventCreateWithFlags(&eFork1, cudaEventDisableTiming);
    cudaEventCreateWithFlags(&eJoin1, cudaEventDisableTiming);
    cudaEventCreateWithFlags(&eFork2, cudaEventDisableTiming);
    cudaEventCreateWithFlags(&eJoin2, cudaEventDisableTiming);

    // Converts (main stream): activations + all 4 weights batched
    f2h4<<<(Bb*Ss*Hh/4 + 255)/256, 256>>>(hiddens, pH,  Bb*Ss*Hh/4);
    f2h4<<<(Bb*Tt*Hh/4 + 255)/256, 256>>>(qh,      pQH, Bb*Tt*Hh/4);
    f2h4w<<<dim3((Hh*Hh/4 + 255)/256, 4), 256>>>(W_q, W_k, W_v, W_o,
                                                 pWq, pWk, pWv, pWo);

    // Fork 1: Q projection on s2 concurrently with K+V projection on main
    cudaEventRecord(eFork1, 0);
    cudaStreamWaitEvent(s2, eFork1, 0);
    gemm16<true , true ><<<dim3(8, 32), 256, GEMM_SMEM, s2>>>(pQH, pWq, b_q, pQ, Bb*Tt, Hh, Hh, 0.125f);
    kvgemm16<<<dim3(8, 128), 256, KV_SMEM>>>(pH, pWk, pWv, pK, pV);
    cudaEventRecord(eJoin1, s2);
    cudaStreamWaitEvent(0, eJoin1, 0);

    // Fused scores + softmax (main)
    scores_softmax<<<dim3(Tt/32, Bb*NH), 512, SS_SMEM>>>(pQ, pK, mask, pP);

    // Fork 2: head-mean on s2 concurrently with AV + O-projection on main
    cudaEventRecord(eFork2, 0);
    cudaStreamWaitEvent(s2, eFork2, 0);
    {
        size_t n8 = (size_t)Bb * Tt * Ss / 8;
        mean_kernel<<<(unsigned)((n8 + 255) / 256), 256, 0, s2>>>(pP, out + (size_t)Bb*Tt*Hh);
    }
    av_f16<<<dim3(Tt/256, Bb*NH), 256, AV_SMEM>>>(pP, pV, pC);
    gemm16<false, true ><<<dim3(8, 32), 256, GEMM_SMEM>>>(pC, pWo, b_o, out, Bb*Tt, Hh, Hh, 1.0f);
    cudaEventRecord(eJoin2, s2);
    cudaStreamWaitEvent(0, eJoin2, 0);

    cudaEventDestroy(eFork1);
    cudaEventDestroy(eJoin1);
    cudaEventDestroy(eFork2);
    cudaEventDestroy(eJoin2);
    cudaStreamDestroy(s2);
}

// round 14
// speedup vs baseline: 1.2169x; 1.0467x over previous
#include <cuda_runtime.h>
#include <cuda_fp16.h>
#include <math.h>
#include <stdint.h>

#define Bb 8
#define Ss 2048
#define Tt 512
#define Hh 1024
#define NH 16
#define DK 64
#define HB (Bb/2)     // half-batch

// ---- scratch ----
__device__ __half g_H [(size_t)Bb*Ss*Hh];
__device__ __half g_QH[(size_t)Bb*Tt*Hh];
__device__ __half g_Wq[Hh*Hh], g_Wk[Hh*Hh], g_Wv[Hh*Hh], g_Wo[Hh*Hh];
__device__ __half g_Q [(size_t)Bb*Tt*Hh];
__device__ __half g_K [(size_t)Bb*Ss*Hh];
__device__ __half g_V [(size_t)Bb*Ss*Hh];
__device__ __half g_P [(size_t)Bb*NH*Tt*Ss];
__device__ __half g_C [(size_t)Bb*Tt*Hh];

// ------------------------------------------------------------
__device__ __forceinline__ uint32_t h2u(__half2 v) { return *(uint32_t*)&v; }

__device__ __forceinline__ void mma_f16(float* c, const uint32_t* a, const uint32_t* b) {
    asm volatile(
        "mma.sync.aligned.m16n8k16.row.col.f32.f16.f16.f32 "
        "{%0,%1,%2,%3}, {%4,%5,%6,%7}, {%8,%9}, {%0,%1,%2,%3};"
        : "+f"(c[0]), "+f"(c[1]), "+f"(c[2]), "+f"(c[3])
        : "r"(a[0]), "r"(a[1]), "r"(a[2]), "r"(a[3]),
          "r"(b[0]), "r"(b[1]));
}

__device__ __forceinline__ void cpa16(void* dst, const void* src) {
    uint32_t d = (uint32_t)__cvta_generic_to_shared(dst);
    asm volatile("cp.async.cg.shared.global [%0], [%1], 16;" :: "r"(d), "l"(src));
}
__device__ __forceinline__ void cp_commit() { asm volatile("cp.async.commit_group;"); }
template<int N_> __device__ __forceinline__ void cp_wait() {
    asm volatile("cp.async.wait_group %0;" :: "n"(N_));
}

__device__ __forceinline__ void ldsm_x4(uint32_t* r, uint32_t addr) {
    asm volatile("ldmatrix.sync.aligned.m8n8.x4.shared.b16 {%0,%1,%2,%3}, [%4];"
        : "=r"(r[0]), "=r"(r[1]), "=r"(r[2]), "=r"(r[3]) : "r"(addr));
}
__device__ __forceinline__ void ldsm_x4_t(uint32_t* r, uint32_t addr) {
    asm volatile("ldmatrix.sync.aligned.m8n8.x4.trans.shared.b16 {%0,%1,%2,%3}, [%4];"
        : "=r"(r[0]), "=r"(r[1]), "=r"(r[2]), "=r"(r[3]) : "r"(addr));
}

__device__ __forceinline__ void ldA_x4(uint32_t* r, const __half* S, int LD,
                                       int row0, int col0, int lane) {
    int g = lane >> 3, rr = lane & 7;
    const __half* p = S + (size_t)(row0 + (g & 1) * 8 + rr) * LD + col0 + (g >> 1) * 8;
    ldsm_x4(r, (uint32_t)__cvta_generic_to_shared(p));
}
__device__ __forceinline__ void ldBn_x4(uint32_t* b0, uint32_t* b1,
                                        const __half* S, int LD, int n0, int k0, int lane) {
    int g = lane >> 3, rr = lane & 7;
    const __half* p = S + (n0 + (g & 1) * 8 + rr) * LD + k0 + (g >> 1) * 8;
    uint32_t q[4];
    ldsm_x4(q, (uint32_t)__cvta_generic_to_shared(p));
    b0[0] = q[0]; b0[1] = q[2];
    b1[0] = q[1]; b1[1] = q[3];
}
__device__ __forceinline__ void ldB_pair(uint32_t* b0, uint32_t* b1,
                                         const __half* S, int RS, int k0, int n0, int lane) {
    int g = lane >> 3, r = lane & 7;
    int row = k0 + r + (g & 1) * 8;
    int col = n0 + (g >> 1) * 8;
    uint32_t q[4];
    ldsm_x4_t(q, (uint32_t)__cvta_generic_to_shared(S + row * RS + col));
    b0[0] = q[0]; b0[1] = q[1];
    b1[0] = q[2]; b1[1] = q[3];
}

// ============================================================
__global__ void f2h4(const float* __restrict__ in, __half* __restrict__ out, int n4) {
    int i = blockIdx.x * blockDim.x + threadIdx.x;
    if (i < n4) {
        float4 v = ((const float4*)in)[i];
        uint2 u;
        u.x = h2u(__floats2half2_rn(v.x, v.y));
        u.y = h2u(__floats2half2_rn(v.z, v.w));
        ((uint2*)out)[i] = u;
    }
}

__global__ void f2h4w(const float* w0, const float* w1,
                      const float* w2, const float* w3,
                      __half* o0, __half* o1, __half* o2, __half* o3)
{
    const int n4 = Hh * Hh / 4;
    int i = blockIdx.x * blockDim.x + threadIdx.x;
    if (i >= n4) return;
    const float* in; __half* out;
    switch (blockIdx.y) {
        case 0: in = w0; out = o0; break;
        case 1: in = w1; out = o1; break;
        case 2: in = w2; out = o2; break;
        default: in = w3; out = o3; break;
    }
    float4 v = ((const float4*)in)[i];
    uint2 u;
    u.x = h2u(__floats2half2_rn(v.x, v.y));
    u.y = h2u(__floats2half2_rn(v.z, v.w));
    ((uint2*)out)[i] = u;
}

// ============================================================
// fp16 GEMM: 128x128 tile, BK=64, cp.async dbl-buf, 8 warps 64x32.
// ============================================================
template<bool F16OUT, bool HAS_BIAS>
__global__ void __launch_bounds__(256) gemm16(
    const __half* __restrict__ A, const __half* __restrict__ W,
    const float* __restrict__ bias, void* __restrict__ Cout,
    int M, int N, int K, float scale)
{
    extern __shared__ __half smx[];
    __half* As = smx;                  // 2 x [128][72]
    __half* Bs = smx + 2 * 128 * 72;   // 2 x [64][136]
    int tid = threadIdx.x, lane = tid & 31, wid = tid >> 5;
    int lr = lane >> 2, lc = lane & 3;
    int wm = (wid >> 2) * 64, wn = (wid & 3) * 32;
    int bx = blockIdx.x, by = blockIdx.y;

    const __half* Ag = A + (size_t)by * 128 * K;
    const __half* Wg = W + bx * 128;

    float acc[4][4][4];
    #pragma unroll
    for (int i = 0; i < 4; i++)
        #pragma unroll
        for (int j = 0; j < 4; j++)
            #pragma unroll
            for (int q = 0; q < 4; q++) acc[i][j][q] = 0.f;

    auto loadAB = [&](int buf, int k0) {
        __half* Ab = As + buf * 128 * 72;
        __half* Bb2 = Bs + buf * 64 * 136;
        #pragma unroll
        for (int j = 0; j < 4; j++) {
            int id = tid + j * 256;
            int r = id >> 3, c = (id & 7) * 8;
            cpa16(Ab + r * 72 + c, Ag + (size_t)r * K + k0 + c);
        }
        #pragma unroll
        for (int j = 0; j < 4; j++) {
            int id = tid + j * 256;
            int r = id >> 4, c = (id & 15) * 8;
            cpa16(Bb2 + r * 136 + c, Wg + (size_t)(k0 + r) * N + c);
        }
        cp_commit();
    };

    int nit = K / 64;
    loadAB(0, 0);
    for (int it = 0; it < nit; it++) {
        if (it + 1 < nit) loadAB((it + 1) & 1, (it + 1) * 64);
        if (it + 1 < nit) cp_wait<1>(); else cp_wait<0>();
        __syncthreads();
        const __half* Ab = As + (it & 1) * 128 * 72;
        const __half* Bb2 = Bs + (it & 1) * 64 * 136;
        #pragma unroll
        for (int ks = 0; ks < 64; ks += 16) {
            uint32_t a[4][4], b[4][2];
            #pragma unroll
            for (int im = 0; im < 4; im++)
                ldA_x4(a[im], Ab, 72, wm + im * 16, ks, lane);
            ldB_pair(b[0], b[1], Bb2, 136, ks, wn,      lane);
            ldB_pair(b[2], b[3], Bb2, 136, ks, wn + 16, lane);
            #pragma unroll
            for (int im = 0; im < 4; im++)
                #pragma unroll
                for (int in_ = 0; in_ < 4; in_++)
                    mma_f16(acc[im][in_], a[im], b[in_]);
        }
        __syncthreads();
    }

    #pragma unroll
    for (int im = 0; im < 4; im++) {
        #pragma unroll
        for (int in_ = 0; in_ < 4; in_++) {
            int r0 = by * 128 + wm + im * 16 + lr;
            int cb = bx * 128 + wn + in_ * 8 + 2 * lc;
            float b0 = HAS_BIAS ? bias[cb] : 0.f;
            float b1 = HAS_BIAS ? bias[cb + 1] : 0.f;
            float x0 = (acc[im][in_][0] + b0) * scale;
            float x1 = (acc[im][in_][1] + b1) * scale;
            float x2 = (acc[im][in_][2] + b0) * scale;
            float x3 = (acc[im][in_][3] + b1) * scale;
            if (F16OUT) {
                __half* C = (__half*)Cout;
                *(__half2*)(C + (size_t)r0 * N + cb)       = __floats2half2_rn(x0, x1);
                *(__half2*)(C + (size_t)(r0 + 8) * N + cb) = __floats2half2_rn(x2, x3);
            } else {
                float* C = (float*)Cout;
                *(float2*)(C + (size_t)r0 * N + cb)       = make_float2(x0, x1);
                *(float2*)(C + (size_t)(r0 + 8) * N + cb) = make_float2(x2, x3);
            }
        }
    }
}

// ============================================================
// Fused K+V projection (legacy HMMA)
// ============================================================
__global__ void __launch_bounds__(256, 1) kvgemm16(
    const __half* __restrict__ A, const __half* __restrict__ Wk,
    const __half* __restrict__ Wv, __half* __restrict__ Ko,
    __half* __restrict__ Vo)
{
    const int N = Hh, K = Hh;
    extern __shared__ __half smk[];
    __half* As  = smk;                    // 2 x [128][72]
    __half* Bks = smk + 2 * 128 * 72;     // 2 x [64][136]
    __half* Bvs = Bks + 2 * 64 * 136;     // 2 x [64][136]
    int tid = threadIdx.x, lane = tid & 31, wid = tid >> 5;
    int lr = lane >> 2, lc = lane & 3;
    int wm = (wid >> 2) * 64, wn = (wid & 3) * 32;
    int bx = blockIdx.x, by = blockIdx.y;

    const __half* Ag  = A  + (size_t)by * 128 * K;
    const __half* Wkg = Wk + bx * 128;
    const __half* Wvg = Wv + bx * 128;

    float accK[4][4][4], accV[4][4][4];
    #pragma unroll
    for (int i = 0; i < 4; i++)
        #pragma unroll
        for (int j = 0; j < 4; j++)
            #pragma unroll
            for (int q = 0; q < 4; q++) { accK[i][j][q] = 0.f; accV[i][j][q] = 0.f; }

    auto loadAB = [&](int buf, int k0) {
        __half* Ab  = As  + buf * 128 * 72;
        __half* Bkb = Bks + buf * 64 * 136;
        __half* Bvb = Bvs + buf * 64 * 136;
        #pragma unroll
        for (int j = 0; j < 4; j++) {
            int id = tid + j * 256;
            int r = id >> 3, c = (id & 7) * 8;
            cpa16(Ab + r * 72 + c, Ag + (size_t)r * K + k0 + c);
        }
        #pragma unroll
        for (int j = 0; j < 4; j++) {
            int id = tid + j * 256;
            int r = id >> 4, c = (id & 15) * 8;
            cpa16(Bkb + r * 136 + c, Wkg + (size_t)(k0 + r) * N + c);
            cpa16(Bvb + r * 136 + c, Wvg + (size_t)(k0 + r) * N + c);
        }
        cp_commit();
    };

    const int nit = K / 64;
    loadAB(0, 0);
    for (int it = 0; it < nit; it++) {
        if (it + 1 < nit) loadAB((it + 1) & 1, (it + 1) * 64);
        if (it + 1 < nit) cp_wait<1>(); else cp_wait<0>();
        __syncthreads();
        const __half* Ab  = As  + (it & 1) * 128 * 72;
        const __half* Bkb = Bks + (it & 1) * 64 * 136;
        const __half* Bvb = Bvs + (it & 1) * 64 * 136;
        #pragma unroll
        for (int ks = 0; ks < 64; ks += 16) {
            uint32_t a[4][4], bk[4][2], bv[4][2];
            #pragma unroll
            for (int im = 0; im < 4; im++)
                ldA_x4(a[im], Ab, 72, wm + im * 16, ks, lane);
            ldB_pair(bk[0], bk[1], Bkb, 136, ks, wn,      lane);
            ldB_pair(bk[2], bk[3], Bkb, 136, ks, wn + 16, lane);
            ldB_pair(bv[0], bv[1], Bvb, 136, ks, wn,      lane);
            ldB_pair(bv[2], bv[3], Bvb, 136, ks, wn + 16, lane);
            #pragma unroll
            for (int im = 0; im < 4; im++)
                #pragma unroll
                for (int in_ = 0; in_ < 4; in_++) {
                    mma_f16(accK[im][in_], a[im], bk[in_]);
                    mma_f16(accV[im][in_], a[im], bv[in_]);
                }
        }
        __syncthreads();
    }

    #pragma unroll
    for (int im = 0; im < 4; im++) {
        #pragma unroll
        for (int in_ = 0; in_ < 4; in_++) {
            int r0 = by * 128 + wm + im * 16 + lr;
            int cb = bx * 128 + wn + in_ * 8 + 2 * lc;
            *(__half2*)(Ko + (size_t)r0 * N + cb) =
                __floats2half2_rn(accK[im][in_][0], accK[im][in_][1]);
            *(__half2*)(Ko + (size_t)(r0 + 8) * N + cb) =
                __floats2half2_rn(accK[im][in_][2], accK[im][in_][3]);
            *(__half2*)(Vo + (size_t)r0 * N + cb) =
                __floats2half2_rn(accV[im][in_][0], accV[im][in_][1]);
            *(__half2*)(Vo + (size_t)(r0 + 8) * N + cb) =
                __floats2half2_rn(accV[im][in_][2], accV[im][in_][3]);
        }
    }
}

// ============================================================
// Fused scores + softmax: 512 threads, 32 t-rows, s-chunk 256.
// bh0 = batch-head offset for half-pipeline split.
// ============================================================
__global__ void __launch_bounds__(512) scores_softmax(
    const __half* __restrict__ Q, const __half* __restrict__ Kg,
    const int* __restrict__ mask, __half* __restrict__ P, int bh0)
{
    extern __shared__ __half sms[];
    __half* Es = sms;                 // [32][2056]
    __half* Ks = sms + 32 * 2056;     // 2 x [256][72]
    __half* Qs = Ks + 2 * 256 * 72;   // [32][72]

    int tid = threadIdx.x, lane = tid & 31, wid = tid >> 5;
    int lr = lane >> 2, lc = lane & 3;
    int bh = blockIdx.y + bh0, b = bh >> 4, h = bh & 15;
    int t0 = blockIdx.x * 32;
    int n0 = wid * 16;

    if (tid < 256) {
        int r = tid >> 3, c = (tid & 7) * 8;
        *(uint4*)&Qs[r * 72 + c] =
            *(const uint4*)(Q + (size_t)(b * Tt + t0 + r) * Hh + h * DK + c);
    }

    auto loadK = [&](int buf, int s0) {
        __half* Kb = Ks + buf * 256 * 72;
        #pragma unroll
        for (int j = 0; j < 4; j++) {
            int id = tid + j * 512;
            int r = id >> 3, c = (id & 7) * 8;
            cpa16(Kb + r * 72 + c, Kg + (size_t)(b * Ss + s0 + r) * Hh + h * DK + c);
        }
        cp_commit();
    };

    loadK(0, 0);
    __syncthreads();

    uint32_t qa[2][4][4];
    #pragma unroll
    for (int im = 0; im < 2; im++)
        #pragma unroll
        for (int kk = 0; kk < 4; kk++)
            ldA_x4(qa[im][kk], Qs, 72, im * 16, kk * 16, lane);

    for (int it = 0; it < 8; it++) {
        if (it + 1 < 8) loadK((it + 1) & 1, (it + 1) * 256);
        if (it + 1 < 8) cp_wait<1>(); else cp_wait<0>();
        __syncthreads();
        const __half* Kb = Ks + (it & 1) * 256 * 72;
        int s0 = it * 256;

        float acc[2][2][4];
        #pragma unroll
        for (int i = 0; i < 2; i++)
            #pragma unroll
            for (int j = 0; j < 2; j++)
                #pragma unroll
                for (int q = 0; q < 4; q++) acc[i][j][q] = 0.f;

        #pragma unroll
        for (int kk = 0; kk < 4; kk++) {
            uint32_t bf[2][2];
            ldBn_x4(bf[0], bf[1], Kb, 72, n0, kk * 16, lane);
            #pragma unroll
            for (int im = 0; im < 2; im++)
                #pragma unroll
                for (int in_ = 0; in_ < 2; in_++)
                    mma_f16(acc[im][in_], qa[im][kk], bf[in_]);
        }

        #pragma unroll
        for (int im = 0; im < 2; im++) {
            #pragma unroll
            for (int in_ = 0; in_ < 2; in_++) {
                int t = im * 16 + lr;
                int s = s0 + n0 + in_ * 8 + 2 * lc;
                *(__half2*)&Es[t * 2056 + s] =
                    __floats2half2_rn(acc[im][in_][0], acc[im][in_][1]);
                *(__half2*)&Es[(t + 8) * 2056 + s] =
                    __floats2half2_rn(acc[im][in_][2], acc[im][in_][3]);
            }
        }
        __syncthreads();
    }

    const int* mrow = mask + b * Ss;
    const __half minus3e4 = __float2half(-30000.f);
    #pragma unroll
    for (int rr = 0; rr < 2; rr++) {
        int r = wid * 2 + rr;
        uint4 E[8];
        float mx = -3.0e38f;
        #pragma unroll
        for (int i = 0; i < 8; i++) {
            int s = i * 256 + lane * 8;
            E[i] = *(uint4*)&Es[r * 2056 + s];
            int4 m0 = *(const int4*)&mrow[s];
            int4 m1 = *(const int4*)&mrow[s + 4];
            __half* hp = (__half*)&E[i];
            if (!m0.x) hp[0] = minus3e4;
            if (!m0.y) hp[1] = minus3e4;
            if (!m0.z) hp[2] = minus3e4;
            if (!m0.w) hp[3] = minus3e4;
            if (!m1.x) hp[4] = minus3e4;
            if (!m1.y) hp[5] = minus3e4;
            if (!m1.z) hp[6] = minus3e4;
            if (!m1.w) hp[7] = minus3e4;
            __half2* h2p = (__half2*)&E[i];
            #pragma unroll
            for (int j = 0; j < 4; j++) {
                float2 f = __half22float2(h2p[j]);
                mx = fmaxf(mx, fmaxf(f.x, f.y));
            }
        }
        #pragma unroll
        for (int o = 16; o; o >>= 1) mx = fmaxf(mx, __shfl_xor_sync(0xffffffffu, mx, o));

        float sum = 0.f;
        #pragma unroll
        for (int i = 0; i < 8; i++) {
            __half2* h2p = (__half2*)&E[i];
            #pragma unroll
            for (int j = 0; j < 4; j++) {
                float2 f = __half22float2(h2p[j]);
                float e0 = __expf(f.x - mx), e1 = __expf(f.y - mx);
                sum += e0 + e1;
                h2p[j] = __floats2half2_rn(e0, e1);
            }
        }
        #pragma unroll
        for (int o = 16; o; o >>= 1) sum += __shfl_xor_sync(0xffffffffu, sum, o);
        float inv = 1.0f / sum;

        __half* Pd = P + ((size_t)bh * Tt + t0 + r) * Ss;
        #pragma unroll
        for (int i = 0; i < 8; i++) {
            __half2* h2p = (__half2*)&E[i];
            #pragma unroll
            for (int j = 0; j < 4; j++) {
                float2 f = __half22float2(h2p[j]);
                h2p[j] = __floats2half2_rn(f.x * inv, f.y * inv);
            }
            int s = i * 256 + lane * 8;
            *(uint4*)(Pd + s) = E[i];
        }
    }
}

// ============================================================
// mean over heads (half-batch variant: nb batches from P/out base)
// ============================================================
__global__ void mean_kernel(const __half* __restrict__ P, float* __restrict__ out, int nb)
{
    const size_t TS = (size_t)Tt * Ss;
    size_t idx = (size_t)blockIdx.x * blockDim.x + threadIdx.x;
    size_t base = idx * 8;
    if (base >= (size_t)nb * TS) return;
    size_t b = base / TS, r = base - b * TS;
    float s[8] = {0,0,0,0,0,0,0,0};
    #pragma unroll
    for (int h = 0; h < NH; h++) {
        uint4 v = *(const uint4*)(P + ((size_t)(b * NH + h)) * TS + r);
        const __half2* hp = (const __half2*)&v;
        #pragma unroll
        for (int j = 0; j < 4; j++) {
            float2 f = __half22float2(hp[j]);
            s[2*j] += f.x; s[2*j+1] += f.y;
        }
    }
    float4 o0 = make_float4(s[0]*0.0625f, s[1]*0.0625f, s[2]*0.0625f, s[3]*0.0625f);
    float4 o1 = make_float4(s[4]*0.0625f, s[5]*0.0625f, s[6]*0.0625f, s[7]*0.0625f);
    *(float4*)(out + base) = o0;
    *(float4*)(out + base + 4) = o1;
}

// ============================================================
// AV v2: block 256(t) x 64(d), 8 warps 4m x 2n, warp 64x32.
// ============================================================
__global__ void __launch_bounds__(256) av_f16(
    const __half* __restrict__ P, const __half* __restrict__ V,
    __half* __restrict__ Cc, int bh0)
{
    extern __shared__ __half smv[];
    __half* Ps = smv;                  // 2 x [256][72]
    __half* Vs = smv + 2 * 256 * 72;   // 2 x [64][72]
    int tid = threadIdx.x, lane = tid & 31, wid = tid >> 5;
    int lr = lane >> 2, lc = lane & 3;
    int wm = (wid >> 1) * 64, wn = (wid & 1) * 32;
    int bh = blockIdx.y + bh0, b = bh >> 4, h = bh & 15;
    int t0 = blockIdx.x * 256;

    float acc[4][4][4];
    #pragma unroll
    for (int i = 0; i < 4; i++)
        #pragma unroll
        for (int j = 0; j < 4; j++)
            #pragma unroll
            for (int q = 0; q < 4; q++) acc[i][j][q] = 0.f;

    const __half* Pbase = P + ((size_t)bh * Tt + t0) * Ss;
    const __half* Vbase = V + (size_t)b * Ss * Hh + h * DK;

    auto loadPV = [&](int buf, int s0) {
        __half* Pb = Ps + buf * 256 * 72;
        __half* Vb = Vs + buf * 64 * 72;
        #pragma unroll
        for (int j = 0; j < 8; j++) {
            int id = tid + j * 256;
            int r = id >> 3, c = (id & 7) * 8;
            cpa16(Pb + r * 72 + c, Pbase + (size_t)r * Ss + s0 + c);
        }
        #pragma unroll
        for (int j = 0; j < 2; j++) {
            int id = tid + j * 256;
            int r = id >> 3, c = (id & 7) * 8;
            cpa16(Vb + r * 72 + c, Vbase + (size_t)(s0 + r) * Hh + c);
        }
        cp_commit();
    };

    loadPV(0, 0);
    for (int it = 0; it < Ss / 64; it++) {
        if (it + 1 < Ss / 64) loadPV((it + 1) & 1, (it + 1) * 64);
        if (it + 1 < Ss / 64) cp_wait<1>(); else cp_wait<0>();
        __syncthreads();
        const __half* Pb = Ps + (it & 1) * 256 * 72;
        const __half* Vb = Vs + (it & 1) * 64 * 72;

        #pragma unroll
        for (int kk = 0; kk < 4; kk++) {
            uint32_t a[4][4], b2[4][2];
            #pragma unroll
            for (int im = 0; im < 4; im++)
                ldA_x4(a[im], Pb, 72, wm + im * 16, kk * 16, lane);
            ldB_pair(b2[0], b2[1], Vb, 72, kk * 16, wn,      lane);
            ldB_pair(b2[2], b2[3], Vb, 72, kk * 16, wn + 16, lane);
            #pragma unroll
            for (int im = 0; im < 4; im++)
                #pragma unroll
                for (int in_ = 0; in_ < 4; in_++)
                    mma_f16(acc[im][in_], a[im], b2[in_]);
        }
        __syncthreads();
    }

    #pragma unroll
    for (int im = 0; im < 4; im++) {
        #pragma unroll
        for (int in_ = 0; in_ < 4; in_++) {
            int r0 = t0 + wm + im * 16 + lr;
            int cb = wn + (in_ & 1) * 8 + (in_ >> 1) * 16 + 2 * lc;
            *(__half2*)(Cc + (size_t)(b * Tt + r0) * Hh + h * DK + cb) =
                __floats2half2_rn(acc[im][in_][0], acc[im][in_][1]);
            *(__half2*)(Cc + (size_t)(b * Tt + r0 + 8) * Hh + h * DK + cb) =
                __floats2half2_rn(acc[im][in_][2], acc[im][in_][3]);
        }
    }
}

// ============================================================
extern "C" void kernel_launch(void* const* d_in, const int* in_sizes, int n_in,
                              void* d_out, int out_size)
{
    const float* hiddens = (const float*)d_in[0];
    const float* qh      = (const float*)d_in[1];
    const int*   mask    = (const int*)  d_in[2];
    const float* W_q     = (const float*)d_in[3];
    const float* b_q     = (const float*)d_in[4];
    const float* W_k     = (const float*)d_in[5];
    const float* W_v     = (const float*)d_in[6];
    const float* W_o     = (const float*)d_in[7];
    const float* b_o     = (const float*)d_in[8];
    float* out = (float*)d_out;

    __half *pH, *pQH, *pWq, *pWk, *pWv, *pWo, *pQ, *pK, *pV, *pP, *pC;
    cudaGetSymbolAddress((void**)&pH,  g_H);
    cudaGetSymbolAddress((void**)&pQH, g_QH);
    cudaGetSymbolAddress((void**)&pWq, g_Wq);
    cudaGetSymbolAddress((void**)&pWk, g_Wk);
    cudaGetSymbolAddress((void**)&pWv, g_Wv);
    cudaGetSymbolAddress((void**)&pWo, g_Wo);
    cudaGetSymbolAddress((void**)&pQ,  g_Q);
    cudaGetSymbolAddress((void**)&pK,  g_K);
    cudaGetSymbolAddress((void**)&pV,  g_V);
    cudaGetSymbolAddress((void**)&pP,  g_P);
    cudaGetSymbolAddress((void**)&pC,  g_C);

    const int GEMM_SMEM = (2*128*72 + 2*64*136) * 2;
    const int KV_SMEM   = (2*128*72 + 4*64*136) * 2;
    const int SS_SMEM   = (32*2056 + 2*256*72 + 32*72) * 2;
    const int AV_SMEM   = (2*256*72 + 2*64*72) * 2;
    cudaFuncSetAttribute(gemm16<true , true >, cudaFuncAttributeMaxDynamicSharedMemorySize, GEMM_SMEM);
    cudaFuncSetAttribute(gemm16<false, true >, cudaFuncAttributeMaxDynamicSharedMemorySize, GEMM_SMEM);
    cudaFuncSetAttribute(kvgemm16, cudaFuncAttributeMaxDynamicSharedMemorySize, KV_SMEM);
    cudaFuncSetAttribute(scores_softmax, cudaFuncAttributeMaxDynamicSharedMemorySize, SS_SMEM);
    cudaFuncSetAttribute(av_f16, cudaFuncAttributeMaxDynamicSharedMemorySize, AV_SMEM);

    cudaStream_t s2;
    cudaEvent_t eFork, eJoin;
    cudaStreamCreateWithFlags(&s2, cudaStreamNonBlocking);
    cudaEventCreateWithFlags(&eFork, cudaEventDisableTiming);
    cudaEventCreateWithFlags(&eJoin, cudaEventDisableTiming);

    // Converts (main stream)
    f2h4<<<(Bb*Ss*Hh/4 + 255)/256, 256>>>(hiddens, pH,  Bb*Ss*Hh/4);
    f2h4<<<(Bb*Tt*Hh/4 + 255)/256, 256>>>(qh,      pQH, Bb*Tt*Hh/4);
    f2h4w<<<dim3((Hh*Hh/4 + 255)/256, 4), 256>>>(W_q, W_k, W_v, W_o,
                                                 pWq, pWk, pWv, pWo);

    cudaEventRecord(eFork, 0);
    cudaStreamWaitEvent(s2, eFork, 0);

    // Offsets for half 1 (batches 4..7)
    const size_t oQH = (size_t)HB * Tt * Hh;           // query hiddens / Q / C rows
    const size_t oH  = (size_t)HB * Ss * Hh;           // hiddens / K / V rows
    const size_t oP  = (size_t)HB * NH * Tt * Ss;      // P
    const size_t oO  = (size_t)HB * Tt * Hh;           // context out rows
    const size_t oM  = (size_t)HB * Tt * Ss;           // mean out
    const int    bh1 = HB * NH;                        // bh offset half 1
    size_t n8h = (size_t)HB * Tt * Ss / 8;

    // ---- half 0 chain on main stream ----
    gemm16<true , true ><<<dim3(8, HB*Tt/128), 256, GEMM_SMEM>>>(
        pQH, pWq, b_q, pQ, HB*Tt, Hh, Hh, 0.125f);
    kvgemm16<<<dim3(8, HB*Ss/128), 256, KV_SMEM>>>(pH, pWk, pWv, pK, pV);
    scores_softmax<<<dim3(Tt/32, HB*NH), 512, SS_SMEM>>>(pQ, pK, mask, pP, 0);
    av_f16<<<dim3(Tt/256, HB*NH), 256, AV_SMEM>>>(pP, pV, pC, 0);
    gemm16<false, true ><<<dim3(8, HB*Tt/128), 256, GEMM_SMEM>>>(
        pC, pWo, b_o, out, HB*Tt, Hh, Hh, 1.0f);
    mean_kernel<<<(unsigned)((n8h + 255) / 256), 256>>>(
        pP, out + (size_t)Bb*Tt*Hh, HB);

    // ---- half 1 chain on s2 ----
    gemm16<true , true ><<<dim3(8, HB*Tt/128), 256, GEMM_SMEM, s2>>>(
        pQH + oQH, pWq, b_q, pQ + oQH, HB*Tt, Hh, Hh, 0.125f);
    kvgemm16<<<dim3(8, HB*Ss/128), 256, KV_SMEM, s2>>>(
        pH + oH, pWk, pWv, pK + oH, pV + oH);
    scores_softmax<<<dim3(Tt/32, HB*NH), 512, SS_SMEM, s2>>>(pQ, pK, mask, pP, bh1);
    av_f16<<<dim3(Tt/256, HB*NH), 256, AV_SMEM, s2>>>(pP, pV, pC, bh1);
    gemm16<false, true ><<<dim3(8, HB*Tt/128), 256, GEMM_SMEM, s2>>>(
        pC + oQH, pWo, b_o, out + oO, HB*Tt, Hh, Hh, 1.0f);
    mean_kernel<<<(unsigned)((n8h + 255) / 256), 256, 0, s2>>>(
        pP + oP, out + (size_t)Bb*Tt*Hh + oM, HB);

    cudaEventRecord(eJoin, s2);
    cudaStreamWaitEvent(0, eJoin, 0);

    cudaEventDestroy(eFork);
    cudaEventDestroy(eJoin);
    cudaStreamDestroy(s2);
}